// round 9
// baseline (speedup 1.0000x reference)
#include <cuda_runtime.h>
#include <cuda_bf16.h>
#include <cstdint>

#define BB   2
#define HH   12
#define NN   2048
#define CC   768
#define DD   64

// Scratch (no allocations allowed)
__device__ float g_q[BB*HH*NN*DD];
__device__ float g_k[BB*HH*NN*DD];
__device__ float g_v[BB*HH*NN*DD];
__device__ float g_att[BB*NN*CC];
__device__ int   g_idx[BB*NN];
__device__ int   g_cnt[BB];

// ---------------------------------------------------------------------------
// mma helpers
// ---------------------------------------------------------------------------
__device__ __forceinline__ void mma_tf32(float* d, const uint32_t* a,
                                         uint32_t b0, uint32_t b1)
{
    asm volatile(
        "mma.sync.aligned.m16n8k8.row.col.f32.tf32.tf32.f32 "
        "{%0,%1,%2,%3},{%4,%5,%6,%7},{%8,%9},{%0,%1,%2,%3};"
        : "+f"(d[0]), "+f"(d[1]), "+f"(d[2]), "+f"(d[3])
        : "r"(a[0]), "r"(a[1]), "r"(a[2]), "r"(a[3]), "r"(b0), "r"(b1));
}

__device__ __forceinline__ void mma_bf16(float* d, const uint32_t* a,
                                         uint32_t b0, uint32_t b1)
{
    asm volatile(
        "mma.sync.aligned.m16n8k16.row.col.f32.bf16.bf16.f32 "
        "{%0,%1,%2,%3},{%4,%5,%6,%7},{%8,%9},{%0,%1,%2,%3};"
        : "+f"(d[0]), "+f"(d[1]), "+f"(d[2]), "+f"(d[3])
        : "r"(a[0]), "r"(a[1]), "r"(a[2]), "r"(a[3]), "r"(b0), "r"(b1));
}

__device__ __forceinline__ uint32_t to_tf32(float f)
{
    uint32_t u;
    asm("cvt.rna.tf32.f32 %0, %1;" : "=r"(u) : "f"(f));
    return u;
}

// split pair (x,y) into packed-bf16 hi word + lo (residual) word
__device__ __forceinline__ void cvt_pair(float x, float y,
                                         uint32_t& hi, uint32_t& lo)
{
    const __nv_bfloat16 hx = __float2bfloat16(x);
    const __nv_bfloat16 hy = __float2bfloat16(y);
    __nv_bfloat162 h; h.x = hx; h.y = hy;
    hi = *reinterpret_cast<uint32_t*>(&h);
    __nv_bfloat162 l;
    l.x = __float2bfloat16(x - __bfloat162float(hx));
    l.y = __float2bfloat16(y - __bfloat162float(hy));
    lo = *reinterpret_cast<uint32_t*>(&l);
}

// ---------------------------------------------------------------------------
// Compaction: per batch, gather indices of visible keys (mask == 0).
// ---------------------------------------------------------------------------
__global__ __launch_bounds__(1024) void compact_kernel(const float* __restrict__ mask)
{
    __shared__ int wsum[32];
    const int b = blockIdx.x;
    const int t = threadIdx.x;
    const int p0 = 2 * t, p1 = 2 * t + 1;
    const int v0 = (mask[b * NN + p0] == 0.0f) ? 1 : 0;
    const int v1 = (mask[b * NN + p1] == 0.0f) ? 1 : 0;
    const int s  = v0 + v1;

    int sc = s;
    #pragma unroll
    for (int o = 1; o < 32; o <<= 1) {
        int n = __shfl_up_sync(0xffffffffu, sc, o);
        if ((t & 31) >= o) sc += n;
    }
    if ((t & 31) == 31) wsum[t >> 5] = sc;
    __syncthreads();
    if (t < 32) {
        int w = wsum[t];
        #pragma unroll
        for (int o = 1; o < 32; o <<= 1) {
            int n = __shfl_up_sync(0xffffffffu, w, o);
            if (t >= o) w += n;
        }
        wsum[t] = w;
    }
    __syncthreads();
    const int excl = (sc - s) + ((t >= 32) ? wsum[(t >> 5) - 1] : 0);
    if (v0) g_idx[b * NN + excl] = p0;
    if (v1) g_idx[b * NN + excl + v0] = p1;
    if (t == 1023) g_cnt[b] = excl + s;
}

// ---------------------------------------------------------------------------
// Tensor-core GEMM, 3xBF16 split (unchanged from R7).
// ---------------------------------------------------------------------------
#define GP 20
#define BUFW (4*128*GP)

template<int MODE>
__global__ __launch_bounds__(256) void gemm_b(const float* __restrict__ A,
                                              const float* __restrict__ W,
                                              const float* __restrict__ bias,
                                              float* __restrict__ out)
{
    extern __shared__ uint32_t su[];

    const int tid = threadIdx.x;
    const int n0 = blockIdx.x * 128;
    const int m0 = blockIdx.y * 128;
    int b = 0, cnt = 0;
    if (MODE == 1) {
        b = blockIdx.z;
        cnt = g_cnt[b];
        if (m0 >= cnt) return;
    }
    const float* Ap = (MODE == 2) ? g_att : A;

    int lrow[4], lw[4];
    size_t a_off[4], b_off[4];
    #pragma unroll
    for (int p = 0; p < 4; p++) {
        const int f = tid + p * 256;
        lrow[p] = f >> 3;
        lw[p]   = (f & 7) * 2;
        const int col4 = (f & 7) * 4;
        if (MODE == 1) {
            const int mrow = m0 + lrow[p];
            const int src  = (mrow < cnt) ? g_idx[b * NN + mrow] : 0;
            a_off[p] = ((size_t)(b * NN + src)) * CC + col4;
        } else {
            a_off[p] = (size_t)(m0 + lrow[p]) * CC + col4;
        }
        b_off[p] = (size_t)(n0 + lrow[p]) * CC + col4;
    }

    const int w = tid >> 5, lane = tid & 31;
    const int wm0 = (w >> 2) * 64;
    const int wn0 = (w & 3) * 32;
    const int lq = lane >> 2;
    const int lr = lane & 3;

    float acc[4][4][4] = {};

    float4 pa[4], pb[4];
    #pragma unroll
    for (int p = 0; p < 4; p++) {
        pa[p] = *(const float4*)(Ap + a_off[p]);
        pb[p] = *(const float4*)(W  + b_off[p]);
    }

    int buf = 0;
    const int NK = CC / 32;
    for (int kt = 0; kt < NK; kt++) {
        uint32_t* AH = su + buf * BUFW;
        uint32_t* AL = AH + 128 * GP;
        uint32_t* BH = AL + 128 * GP;
        uint32_t* BL = BH + 128 * GP;

        #pragma unroll
        for (int p = 0; p < 4; p++) {
            uint32_t h0, l0, h1, l1;
            cvt_pair(pa[p].x, pa[p].y, h0, l0);
            cvt_pair(pa[p].z, pa[p].w, h1, l1);
            *(uint2*)&AH[lrow[p] * GP + lw[p]] = make_uint2(h0, h1);
            *(uint2*)&AL[lrow[p] * GP + lw[p]] = make_uint2(l0, l1);
            cvt_pair(pb[p].x, pb[p].y, h0, l0);
            cvt_pair(pb[p].z, pb[p].w, h1, l1);
            *(uint2*)&BH[lrow[p] * GP + lw[p]] = make_uint2(h0, h1);
            *(uint2*)&BL[lrow[p] * GP + lw[p]] = make_uint2(l0, l1);
        }
        __syncthreads();

        if (kt + 1 < NK) {
            #pragma unroll
            for (int p = 0; p < 4; p++) {
                pa[p] = *(const float4*)(Ap + a_off[p] + (kt + 1) * 32);
                pb[p] = *(const float4*)(W  + b_off[p] + (kt + 1) * 32);
            }
        }

        #pragma unroll
        for (int kb = 0; kb < 2; kb++) {
            const int wb = kb * 8;
            uint32_t aH[4][4], aL[4][4];
            #pragma unroll
            for (int i = 0; i < 4; i++) {
                const int r = wm0 + i * 16 + lq;
                aH[i][0] = AH[r * GP + wb + lr];
                aH[i][1] = AH[(r + 8) * GP + wb + lr];
                aH[i][2] = AH[r * GP + wb + 4 + lr];
                aH[i][3] = AH[(r + 8) * GP + wb + 4 + lr];
                aL[i][0] = AL[r * GP + wb + lr];
                aL[i][1] = AL[(r + 8) * GP + wb + lr];
                aL[i][2] = AL[r * GP + wb + 4 + lr];
                aL[i][3] = AL[(r + 8) * GP + wb + 4 + lr];
            }
            uint32_t bH[4][2], bL[4][2];
            #pragma unroll
            for (int j = 0; j < 4; j++) {
                const int n = wn0 + j * 8 + lq;
                bH[j][0] = BH[n * GP + wb + lr];
                bH[j][1] = BH[n * GP + wb + 4 + lr];
                bL[j][0] = BL[n * GP + wb + lr];
                bL[j][1] = BL[n * GP + wb + 4 + lr];
            }
            #pragma unroll
            for (int i = 0; i < 4; i++)
                #pragma unroll
                for (int j = 0; j < 4; j++) {
                    mma_bf16(acc[i][j], aH[i], bH[j][0], bH[j][1]);
                    mma_bf16(acc[i][j], aH[i], bL[j][0], bL[j][1]);
                    mma_bf16(acc[i][j], aL[i], bH[j][0], bH[j][1]);
                }
        }
        __syncthreads();
        buf ^= 1;
    }

    #pragma unroll
    for (int i = 0; i < 4; i++) {
        #pragma unroll
        for (int half = 0; half < 2; half++) {
            const int m = m0 + wm0 + i * 16 + lq + half * 8;
            if (MODE == 1 && m >= cnt) continue;
            #pragma unroll
            for (int j = 0; j < 4; j++) {
                const int c  = n0 + wn0 + j * 8 + 2 * lr;
                const float v0 = acc[i][j][half * 2];
                const float v1 = acc[i][j][half * 2 + 1];
                if (MODE == 0) {
                    const int bpos = m >> 11, nn = m & 2047;
                    const int h = c >> 6, d = c & 63;
                    *(float2*)&g_q[(((size_t)bpos * HH + h) * NN + nn) * DD + d] =
                        make_float2(v0, v1);
                } else if (MODE == 1) {
                    const bool isv = (c >= 768);
                    const int cc2 = isv ? (c - 768) : c;
                    const int h = cc2 >> 6, d = cc2 & 63;
                    float* dst = isv ? g_v : g_k;
                    *(float2*)&dst[(((size_t)b * HH + h) * NN + m) * DD + d] =
                        make_float2(v0, v1);
                } else {
                    *(float2*)&out[(size_t)m * CC + c] =
                        make_float2(v0 + bias[c], v1 + bias[c + 1]);
                }
            }
        }
    }
}

// ---------------------------------------------------------------------------
// Flash attention, tf32 mma.sync, FRAGMENT-MAJOR K/V smem layouts.
// Same numerics/order as R7 (bit-identical output), far fewer LDS instrs.
//   KF[(nt*32 + lane)*20 + kc*2 + w] = K[nt*8+lq][kc*8+lr+4w]
//   VF[(kc*32 + lane)*20 + dt*2 + w] = V[kc*8+lr+4w][dt*8+lq]
// Ps: per-warp 16x68 P tile (also used once to stage Q, pitch 68).
// ---------------------------------------------------------------------------
#define QSP 68
#define KFW 5120   // 8*32*20 words
#define PSW 4352   // 64*68 words

__global__ __launch_bounds__(128) void attn_kernel()
{
    extern __shared__ uint32_t smu[];
    uint32_t* KF = smu;
    uint32_t* VF = KF + KFW;
    float*    Ps = (float*)(VF + KFW);

    const int tid  = threadIdx.x;
    const int w    = tid >> 5, lane = tid & 31;
    const int lq   = lane >> 2;
    const int lr   = lane & 3;
    const int q0   = blockIdx.x * 64;
    const int h    = blockIdx.y;
    const int b    = blockIdx.z;
    const int cnt  = g_cnt[b];
    const size_t base = ((size_t)(b * HH + h)) * NN * DD;
    float* Pw = Ps + w * 16 * QSP;

    // Stage Q (pitch 68) into Ps region; each warp reads only its own 16 rows,
    // which it alone later overwrites with P -> single sync suffices.
    for (int e = tid * 4; e < 64 * 64; e += 512) {
        const int r = e >> 6, c = e & 63;
        *(float4*)(Ps + r * QSP + c) =
            *(const float4*)(g_q + base + (size_t)(q0 + r) * DD + c);
    }
    __syncthreads();
    uint32_t qa[8][4];
    #pragma unroll
    for (int kc = 0; kc < 8; kc++) {
        const int r0 = w * 16 + lq;
        qa[kc][0] = to_tf32(Ps[r0 * QSP + kc * 8 + lr] * 0.125f);
        qa[kc][1] = to_tf32(Ps[(r0 + 8) * QSP + kc * 8 + lr] * 0.125f);
        qa[kc][2] = to_tf32(Ps[r0 * QSP + kc * 8 + lr + 4] * 0.125f);
        qa[kc][3] = to_tf32(Ps[(r0 + 8) * QSP + kc * 8 + lr + 4] * 0.125f);
    }

    float o[8][4] = {};
    float m0 = -1e30f, m1 = -1e30f, l0 = 0.f, l1 = 0.f;
    const float4 z4 = make_float4(0.f, 0.f, 0.f, 0.f);

    for (int kt = 0; kt < cnt; kt += 64) {
        __syncthreads();   // prior tile's KF/VF consumers done
        for (int e = tid * 4; e < 64 * 64; e += 512) {
            const int r = e >> 6, c = e & 63;
            const int gr = kt + r;
            float4 k4 = z4, v4 = z4;
            if (gr < cnt) {
                k4 = *(const float4*)(g_k + base + (size_t)gr * DD + c);
                v4 = *(const float4*)(g_v + base + (size_t)gr * DD + c);
            }
            // K scatter: nt=r>>3, lq_k=r&7, kc=c>>3, w_k=(c&7)>>2; lr = 0..3
            {
                const int kb = ((r >> 3) * 32 + (r & 7) * 4) * 20
                             + (c >> 3) * 2 + ((c & 7) >> 2);
                KF[kb]      = __float_as_uint(k4.x);
                KF[kb + 20] = __float_as_uint(k4.y);
                KF[kb + 40] = __float_as_uint(k4.z);
                KF[kb + 60] = __float_as_uint(k4.w);
            }
            // V scatter: kc=r>>3, lr_v=(r&7)&3, w_v=(r&7)>>2, dt=c>>3, lq_v=(c&7)+m
            {
                const int rr = r & 7;
                const int vb = ((r >> 3) * 32 + (c & 7) * 4 + (rr & 3)) * 20
                             + (c >> 3) * 2 + (rr >> 2);
                VF[vb]       = __float_as_uint(v4.x);
                VF[vb + 80]  = __float_as_uint(v4.y);
                VF[vb + 160] = __float_as_uint(v4.z);
                VF[vb + 240] = __float_as_uint(v4.w);
            }
        }
        __syncthreads();

        // Phase A: S = Q @ K^T -- B-fragments via 4x LDS.128 per nt
        float s[8][4];
        #pragma unroll
        for (int nt = 0; nt < 8; nt++) {
            const uint32_t* kfp = KF + (nt * 32 + lane) * 20;
            uint4 f0 = *(const uint4*)(kfp);
            uint4 f1 = *(const uint4*)(kfp + 4);
            uint4 f2 = *(const uint4*)(kfp + 8);
            uint4 f3 = *(const uint4*)(kfp + 12);
            s[nt][0] = s[nt][1] = s[nt][2] = s[nt][3] = 0.f;
            mma_tf32(s[nt], qa[0], f0.x, f0.y);
            mma_tf32(s[nt], qa[1], f0.z, f0.w);
            mma_tf32(s[nt], qa[2], f1.x, f1.y);
            mma_tf32(s[nt], qa[3], f1.z, f1.w);
            mma_tf32(s[nt], qa[4], f2.x, f2.y);
            mma_tf32(s[nt], qa[5], f2.z, f2.w);
            mma_tf32(s[nt], qa[6], f3.x, f3.y);
            mma_tf32(s[nt], qa[7], f3.z, f3.w);
        }

        // Online softmax (identical to R7)
        float mx0 = -1e30f, mx1 = -1e30f;
        #pragma unroll
        for (int nt = 0; nt < 8; nt++) {
            const int col = kt + nt * 8 + 2 * lr;
            if (col >= cnt)     { s[nt][0] = -1e30f; s[nt][2] = -1e30f; }
            if (col + 1 >= cnt) { s[nt][1] = -1e30f; s[nt][3] = -1e30f; }
            mx0 = fmaxf(mx0, fmaxf(s[nt][0], s[nt][1]));
            mx1 = fmaxf(mx1, fmaxf(s[nt][2], s[nt][3]));
        }
        mx0 = fmaxf(mx0, __shfl_xor_sync(0xffffffffu, mx0, 1));
        mx0 = fmaxf(mx0, __shfl_xor_sync(0xffffffffu, mx0, 2));
        mx1 = fmaxf(mx1, __shfl_xor_sync(0xffffffffu, mx1, 1));
        mx1 = fmaxf(mx1, __shfl_xor_sync(0xffffffffu, mx1, 2));
        const float mn0 = fmaxf(m0, mx0), mn1 = fmaxf(m1, mx1);
        const float al0 = __expf(m0 - mn0), al1 = __expf(m1 - mn1);
        m0 = mn0; m1 = mn1;

        float ls0 = 0.f, ls1 = 0.f;
        #pragma unroll
        for (int nt = 0; nt < 8; nt++) {
            const float p0 = __expf(s[nt][0] - mn0);
            const float p1 = __expf(s[nt][1] - mn0);
            const float p2 = __expf(s[nt][2] - mn1);
            const float p3 = __expf(s[nt][3] - mn1);
            ls0 += p0 + p1; ls1 += p2 + p3;
            const int c0 = nt * 8 + 2 * lr;
            *(float2*)&Pw[lq * QSP + c0] =
                make_float2(__uint_as_float(to_tf32(p0)), __uint_as_float(to_tf32(p1)));
            *(float2*)&Pw[(lq + 8) * QSP + c0] =
                make_float2(__uint_as_float(to_tf32(p2)), __uint_as_float(to_tf32(p3)));
        }
        ls0 += __shfl_xor_sync(0xffffffffu, ls0, 1);
        ls0 += __shfl_xor_sync(0xffffffffu, ls0, 2);
        ls1 += __shfl_xor_sync(0xffffffffu, ls1, 1);
        ls1 += __shfl_xor_sync(0xffffffffu, ls1, 2);
        l0 = l0 * al0 + ls0;
        l1 = l1 * al1 + ls1;
        #pragma unroll
        for (int dt = 0; dt < 8; dt++) {
            o[dt][0] *= al0; o[dt][1] *= al0;
            o[dt][2] *= al1; o[dt][3] *= al1;
        }
        __syncwarp();

        // Phase B: O += P @ V -- V-fragments via 4x LDS.128 per kc
        #pragma unroll
        for (int kc = 0; kc < 8; kc++) {
            uint32_t pa[4];
            pa[0] = __float_as_uint(Pw[lq * QSP + kc * 8 + lr]);
            pa[1] = __float_as_uint(Pw[(lq + 8) * QSP + kc * 8 + lr]);
            pa[2] = __float_as_uint(Pw[lq * QSP + kc * 8 + lr + 4]);
            pa[3] = __float_as_uint(Pw[(lq + 8) * QSP + kc * 8 + lr + 4]);
            const uint32_t* vfp = VF + (kc * 32 + lane) * 20;
            uint4 g0 = *(const uint4*)(vfp);
            uint4 g1 = *(const uint4*)(vfp + 4);
            uint4 g2 = *(const uint4*)(vfp + 8);
            uint4 g3 = *(const uint4*)(vfp + 12);
            mma_tf32(o[0], pa, g0.x, g0.y);
            mma_tf32(o[1], pa, g0.z, g0.w);
            mma_tf32(o[2], pa, g1.x, g1.y);
            mma_tf32(o[3], pa, g1.z, g1.w);
            mma_tf32(o[4], pa, g2.x, g2.y);
            mma_tf32(o[5], pa, g2.z, g2.w);
            mma_tf32(o[6], pa, g3.x, g3.y);
            mma_tf32(o[7], pa, g3.z, g3.w);
        }
        __syncwarp();
    }

    const float inv0 = 1.0f / l0, inv1 = 1.0f / l1;
    const int r0 = q0 + w * 16 + lq, r1 = r0 + 8;
    #pragma unroll
    for (int dt = 0; dt < 8; dt++) {
        const int d = h * 64 + dt * 8 + 2 * lr;
        *(float2*)(g_att + ((size_t)(b * NN + r0)) * CC + d) =
            make_float2(o[dt][0] * inv0, o[dt][1] * inv0);
        *(float2*)(g_att + ((size_t)(b * NN + r1)) * CC + d) =
            make_float2(o[dt][2] * inv1, o[dt][3] * inv1);
    }
}

// ---------------------------------------------------------------------------

extern "C" void kernel_launch(void* const* d_in, const int* in_sizes, int n_in,
                              void* d_out, int out_size)
{
    const float* x      = (const float*)d_in[0];
    const float* mask   = (const float*)d_in[1];
    const float* qkv_w  = (const float*)d_in[2];
    const float* proj_w = (const float*)d_in[3];
    const float* proj_b = (const float*)d_in[4];
    float* out = (float*)d_out;

    const int smem_attn = (2 * KFW + PSW) * (int)sizeof(uint32_t);  // 58,368 B
    cudaFuncSetAttribute(attn_kernel,
                         cudaFuncAttributeMaxDynamicSharedMemorySize, smem_attn);

    const int smem_gemm = 2 * BUFW * (int)sizeof(uint32_t);         // 81,920 B
    cudaFuncSetAttribute(gemm_b<0>,
                         cudaFuncAttributeMaxDynamicSharedMemorySize, smem_gemm);
    cudaFuncSetAttribute(gemm_b<1>,
                         cudaFuncAttributeMaxDynamicSharedMemorySize, smem_gemm);
    cudaFuncSetAttribute(gemm_b<2>,
                         cudaFuncAttributeMaxDynamicSharedMemorySize, smem_gemm);

    compact_kernel<<<BB, 1024>>>(mask);
    gemm_b<0><<<dim3(CC / 128, (BB * NN) / 128), 256, smem_gemm>>>(
        x, qkv_w, nullptr, nullptr);
    gemm_b<1><<<dim3(2 * CC / 128, NN / 128, BB), 256, smem_gemm>>>(
        x, qkv_w + 768 * CC, nullptr, nullptr);
    attn_kernel<<<dim3(NN / 64, HH, BB), 128, smem_attn>>>();
    gemm_b<2><<<dim3(CC / 128, (BB * NN) / 128), 256, smem_gemm>>>(
        nullptr, proj_w, proj_b, out);
}

// round 10
// speedup vs baseline: 1.0423x; 1.0423x over previous
#include <cuda_runtime.h>
#include <cuda_bf16.h>
#include <cstdint>

#define BB   2
#define HH   12
#define NN   2048
#define CC   768
#define DD   64

// Scratch (no allocations allowed)
__device__ float g_q[BB*HH*NN*DD];
__device__ float g_k[BB*HH*NN*DD];
__device__ float g_v[BB*HH*NN*DD];
__device__ float g_att[BB*NN*CC];
__device__ int   g_idx[BB*NN];
__device__ int   g_cnt[BB];

// ---------------------------------------------------------------------------
// mma helpers
// ---------------------------------------------------------------------------
__device__ __forceinline__ void mma_tf32(float* d, const uint32_t* a,
                                         uint32_t b0, uint32_t b1)
{
    asm volatile(
        "mma.sync.aligned.m16n8k8.row.col.f32.tf32.tf32.f32 "
        "{%0,%1,%2,%3},{%4,%5,%6,%7},{%8,%9},{%0,%1,%2,%3};"
        : "+f"(d[0]), "+f"(d[1]), "+f"(d[2]), "+f"(d[3])
        : "r"(a[0]), "r"(a[1]), "r"(a[2]), "r"(a[3]), "r"(b0), "r"(b1));
}

__device__ __forceinline__ void mma_bf16(float* d, const uint32_t* a,
                                         uint32_t b0, uint32_t b1)
{
    asm volatile(
        "mma.sync.aligned.m16n8k16.row.col.f32.bf16.bf16.f32 "
        "{%0,%1,%2,%3},{%4,%5,%6,%7},{%8,%9},{%0,%1,%2,%3};"
        : "+f"(d[0]), "+f"(d[1]), "+f"(d[2]), "+f"(d[3])
        : "r"(a[0]), "r"(a[1]), "r"(a[2]), "r"(a[3]), "r"(b0), "r"(b1));
}

__device__ __forceinline__ uint32_t to_tf32(float f)
{
    uint32_t u;
    asm("cvt.rna.tf32.f32 %0, %1;" : "=r"(u) : "f"(f));
    return u;
}

// split pair (x,y) into packed-bf16 hi word + lo (residual) word
__device__ __forceinline__ void cvt_pair(float x, float y,
                                         uint32_t& hi, uint32_t& lo)
{
    const __nv_bfloat16 hx = __float2bfloat16(x);
    const __nv_bfloat16 hy = __float2bfloat16(y);
    __nv_bfloat162 h; h.x = hx; h.y = hy;
    hi = *reinterpret_cast<uint32_t*>(&h);
    __nv_bfloat162 l;
    l.x = __float2bfloat16(x - __bfloat162float(hx));
    l.y = __float2bfloat16(y - __bfloat162float(hy));
    lo = *reinterpret_cast<uint32_t*>(&l);
}

// ---------------------------------------------------------------------------
// Compaction: per batch, gather indices of visible keys (mask == 0).
// ---------------------------------------------------------------------------
__global__ __launch_bounds__(1024) void compact_kernel(const float* __restrict__ mask)
{
    __shared__ int wsum[32];
    const int b = blockIdx.x;
    const int t = threadIdx.x;
    const int p0 = 2 * t, p1 = 2 * t + 1;
    const int v0 = (mask[b * NN + p0] == 0.0f) ? 1 : 0;
    const int v1 = (mask[b * NN + p1] == 0.0f) ? 1 : 0;
    const int s  = v0 + v1;

    int sc = s;
    #pragma unroll
    for (int o = 1; o < 32; o <<= 1) {
        int n = __shfl_up_sync(0xffffffffu, sc, o);
        if ((t & 31) >= o) sc += n;
    }
    if ((t & 31) == 31) wsum[t >> 5] = sc;
    __syncthreads();
    if (t < 32) {
        int w = wsum[t];
        #pragma unroll
        for (int o = 1; o < 32; o <<= 1) {
            int n = __shfl_up_sync(0xffffffffu, w, o);
            if (t >= o) w += n;
        }
        wsum[t] = w;
    }
    __syncthreads();
    const int excl = (sc - s) + ((t >= 32) ? wsum[(t >> 5) - 1] : 0);
    if (v0) g_idx[b * NN + excl] = p0;
    if (v1) g_idx[b * NN + excl + v0] = p1;
    if (t == 1023) g_cnt[b] = excl + s;
}

// ---------------------------------------------------------------------------
// Tensor-core GEMM, 3xBF16 split (unchanged from R7).
// ---------------------------------------------------------------------------
#define GP 20
#define BUFW (4*128*GP)

template<int MODE>
__global__ __launch_bounds__(256) void gemm_b(const float* __restrict__ A,
                                              const float* __restrict__ W,
                                              const float* __restrict__ bias,
                                              float* __restrict__ out)
{
    extern __shared__ uint32_t su[];

    const int tid = threadIdx.x;
    const int n0 = blockIdx.x * 128;
    const int m0 = blockIdx.y * 128;
    int b = 0, cnt = 0;
    if (MODE == 1) {
        b = blockIdx.z;
        cnt = g_cnt[b];
        if (m0 >= cnt) return;
    }
    const float* Ap = (MODE == 2) ? g_att : A;

    int lrow[4], lw[4];
    size_t a_off[4], b_off[4];
    #pragma unroll
    for (int p = 0; p < 4; p++) {
        const int f = tid + p * 256;
        lrow[p] = f >> 3;
        lw[p]   = (f & 7) * 2;
        const int col4 = (f & 7) * 4;
        if (MODE == 1) {
            const int mrow = m0 + lrow[p];
            const int src  = (mrow < cnt) ? g_idx[b * NN + mrow] : 0;
            a_off[p] = ((size_t)(b * NN + src)) * CC + col4;
        } else {
            a_off[p] = (size_t)(m0 + lrow[p]) * CC + col4;
        }
        b_off[p] = (size_t)(n0 + lrow[p]) * CC + col4;
    }

    const int w = tid >> 5, lane = tid & 31;
    const int wm0 = (w >> 2) * 64;
    const int wn0 = (w & 3) * 32;
    const int lq = lane >> 2;
    const int lr = lane & 3;

    float acc[4][4][4] = {};

    float4 pa[4], pb[4];
    #pragma unroll
    for (int p = 0; p < 4; p++) {
        pa[p] = *(const float4*)(Ap + a_off[p]);
        pb[p] = *(const float4*)(W  + b_off[p]);
    }

    int buf = 0;
    const int NK = CC / 32;
    for (int kt = 0; kt < NK; kt++) {
        uint32_t* AH = su + buf * BUFW;
        uint32_t* AL = AH + 128 * GP;
        uint32_t* BH = AL + 128 * GP;
        uint32_t* BL = BH + 128 * GP;

        #pragma unroll
        for (int p = 0; p < 4; p++) {
            uint32_t h0, l0, h1, l1;
            cvt_pair(pa[p].x, pa[p].y, h0, l0);
            cvt_pair(pa[p].z, pa[p].w, h1, l1);
            *(uint2*)&AH[lrow[p] * GP + lw[p]] = make_uint2(h0, h1);
            *(uint2*)&AL[lrow[p] * GP + lw[p]] = make_uint2(l0, l1);
            cvt_pair(pb[p].x, pb[p].y, h0, l0);
            cvt_pair(pb[p].z, pb[p].w, h1, l1);
            *(uint2*)&BH[lrow[p] * GP + lw[p]] = make_uint2(h0, h1);
            *(uint2*)&BL[lrow[p] * GP + lw[p]] = make_uint2(l0, l1);
        }
        __syncthreads();

        if (kt + 1 < NK) {
            #pragma unroll
            for (int p = 0; p < 4; p++) {
                pa[p] = *(const float4*)(Ap + a_off[p] + (kt + 1) * 32);
                pb[p] = *(const float4*)(W  + b_off[p] + (kt + 1) * 32);
            }
        }

        #pragma unroll
        for (int kb = 0; kb < 2; kb++) {
            const int wb = kb * 8;
            uint32_t aH[4][4], aL[4][4];
            #pragma unroll
            for (int i = 0; i < 4; i++) {
                const int r = wm0 + i * 16 + lq;
                aH[i][0] = AH[r * GP + wb + lr];
                aH[i][1] = AH[(r + 8) * GP + wb + lr];
                aH[i][2] = AH[r * GP + wb + 4 + lr];
                aH[i][3] = AH[(r + 8) * GP + wb + 4 + lr];
                aL[i][0] = AL[r * GP + wb + lr];
                aL[i][1] = AL[(r + 8) * GP + wb + lr];
                aL[i][2] = AL[r * GP + wb + 4 + lr];
                aL[i][3] = AL[(r + 8) * GP + wb + 4 + lr];
            }
            uint32_t bH[4][2], bL[4][2];
            #pragma unroll
            for (int j = 0; j < 4; j++) {
                const int n = wn0 + j * 8 + lq;
                bH[j][0] = BH[n * GP + wb + lr];
                bH[j][1] = BH[n * GP + wb + 4 + lr];
                bL[j][0] = BL[n * GP + wb + lr];
                bL[j][1] = BL[n * GP + wb + 4 + lr];
            }
            #pragma unroll
            for (int i = 0; i < 4; i++)
                #pragma unroll
                for (int j = 0; j < 4; j++) {
                    mma_bf16(acc[i][j], aH[i], bH[j][0], bH[j][1]);
                    mma_bf16(acc[i][j], aH[i], bL[j][0], bL[j][1]);
                    mma_bf16(acc[i][j], aL[i], bH[j][0], bH[j][1]);
                }
        }
        __syncthreads();
        buf ^= 1;
    }

    #pragma unroll
    for (int i = 0; i < 4; i++) {
        #pragma unroll
        for (int half = 0; half < 2; half++) {
            const int m = m0 + wm0 + i * 16 + lq + half * 8;
            if (MODE == 1 && m >= cnt) continue;
            #pragma unroll
            for (int j = 0; j < 4; j++) {
                const int c  = n0 + wn0 + j * 8 + 2 * lr;
                const float v0 = acc[i][j][half * 2];
                const float v1 = acc[i][j][half * 2 + 1];
                if (MODE == 0) {
                    const int bpos = m >> 11, nn = m & 2047;
                    const int h = c >> 6, d = c & 63;
                    *(float2*)&g_q[(((size_t)bpos * HH + h) * NN + nn) * DD + d] =
                        make_float2(v0, v1);
                } else if (MODE == 1) {
                    const bool isv = (c >= 768);
                    const int cc2 = isv ? (c - 768) : c;
                    const int h = cc2 >> 6, d = cc2 & 63;
                    float* dst = isv ? g_v : g_k;
                    *(float2*)&dst[(((size_t)b * HH + h) * NN + m) * DD + d] =
                        make_float2(v0, v1);
                } else {
                    *(float2*)&out[(size_t)m * CC + c] =
                        make_float2(v0 + bias[c], v1 + bias[c + 1]);
                }
            }
        }
    }
}

// ---------------------------------------------------------------------------
// Flash attention, tf32 mma.sync, cp.async DOUBLE-BUFFERED K/V tiles.
// P tile aliases the current (consumed) K buffer -> 2 full buffers in 70KB,
// 3 blocks/SM retained. Numerics identical to R7/R9 (bit-identical output).
// ---------------------------------------------------------------------------
#define KP 68
#define VP 72
#define KBW (64*KP)   // 4352 floats per K buffer
#define VBW (64*VP)   // 4608 floats per V buffer

__global__ __launch_bounds__(128) void attn_kernel()
{
    extern __shared__ float sm[];
    float* KB = sm;              // 2 x 64 x KP
    float* VB = sm + 2 * KBW;    // 2 x 64 x VP

    const int tid  = threadIdx.x;
    const int w    = tid >> 5, lane = tid & 31;
    const int lq   = lane >> 2;
    const int lr   = lane & 3;
    const int q0   = blockIdx.x * 64;
    const int h    = blockIdx.y;
    const int b    = blockIdx.z;
    const int cnt  = g_cnt[b];
    const size_t base = ((size_t)(b * HH + h)) * NN * DD;

    // ---- Stage Q into KB[0], extract loop-invariant pre-scaled A-fragments
    for (int e = tid * 4; e < 64 * 64; e += 512) {
        const int r = e >> 6, c = e & 63;
        *(float4*)(KB + r * KP + c) =
            *(const float4*)(g_q + base + (size_t)(q0 + r) * DD + c);
    }
    __syncthreads();
    uint32_t qa[8][4];
    #pragma unroll
    for (int kc = 0; kc < 8; kc++) {
        const int r0 = w * 16 + lq;
        qa[kc][0] = to_tf32(KB[r0 * KP + kc * 8 + lr] * 0.125f);
        qa[kc][1] = to_tf32(KB[(r0 + 8) * KP + kc * 8 + lr] * 0.125f);
        qa[kc][2] = to_tf32(KB[r0 * KP + kc * 8 + lr + 4] * 0.125f);
        qa[kc][3] = to_tf32(KB[(r0 + 8) * KP + kc * 8 + lr + 4] * 0.125f);
    }
    __syncthreads();

    // ---- cp.async tile loader (zero-fill past cnt) ----
    auto issue_tile = [&](int kt, int bufi) {
        float* Kb = KB + bufi * KBW;
        float* Vb = VB + bufi * VBW;
        #pragma unroll
        for (int e = tid * 4; e < 64 * 64; e += 512) {
            const int r = e >> 6, c = e & 63;
            const int gr = kt + r;
            const int sz = (gr < cnt) ? 16 : 0;
            const int grc = (gr < NN) ? gr : (NN - 1);
            const float* ksrc = g_k + base + (size_t)grc * DD + c;
            const float* vsrc = g_v + base + (size_t)grc * DD + c;
            const uint32_t ka = (uint32_t)__cvta_generic_to_shared(Kb + r * KP + c);
            const uint32_t va = (uint32_t)__cvta_generic_to_shared(Vb + r * VP + c);
            asm volatile("cp.async.ca.shared.global [%0], [%1], 16, %2;"
                         :: "r"(ka), "l"(ksrc), "r"(sz));
            asm volatile("cp.async.ca.shared.global [%0], [%1], 16, %2;"
                         :: "r"(va), "l"(vsrc), "r"(sz));
        }
    };

    const int ntk = (cnt + 63) >> 6;
    issue_tile(0, 0);
    asm volatile("cp.async.commit_group;" ::: "memory");
    if (ntk > 1) issue_tile(64, 1);
    asm volatile("cp.async.commit_group;" ::: "memory");

    float o[8][4] = {};
    float m0 = -1e30f, m1 = -1e30f, l0 = 0.f, l1 = 0.f;

    for (int t = 0; t < ntk; t++) {
        asm volatile("cp.async.wait_group 1;" ::: "memory");
        __syncthreads();
        const int  kt = t * 64;
        const int  cur = t & 1;
        float* Ks = KB + cur * KBW;
        float* Vs = VB + cur * VBW;
        float* Pw = Ks + w * 16 * KP;   // P aliases consumed K rows

        // Phase A: S = Q @ K^T
        float s[8][4];
        #pragma unroll
        for (int nt = 0; nt < 8; nt++) {
            s[nt][0] = s[nt][1] = s[nt][2] = s[nt][3] = 0.f;
            #pragma unroll
            for (int kc = 0; kc < 8; kc++) {
                const uint32_t b0 =
                    __float_as_uint(Ks[(nt * 8 + lq) * KP + kc * 8 + lr]);
                const uint32_t b1 =
                    __float_as_uint(Ks[(nt * 8 + lq) * KP + kc * 8 + lr + 4]);
                mma_tf32(s[nt], qa[kc], b0, b1);
            }
        }
        __syncthreads();   // all warps done reading K -> safe to alias P

        // Online softmax (identical ordering to R7/R9)
        float mx0 = -1e30f, mx1 = -1e30f;
        #pragma unroll
        for (int nt = 0; nt < 8; nt++) {
            const int col = kt + nt * 8 + 2 * lr;
            if (col >= cnt)     { s[nt][0] = -1e30f; s[nt][2] = -1e30f; }
            if (col + 1 >= cnt) { s[nt][1] = -1e30f; s[nt][3] = -1e30f; }
            mx0 = fmaxf(mx0, fmaxf(s[nt][0], s[nt][1]));
            mx1 = fmaxf(mx1, fmaxf(s[nt][2], s[nt][3]));
        }
        mx0 = fmaxf(mx0, __shfl_xor_sync(0xffffffffu, mx0, 1));
        mx0 = fmaxf(mx0, __shfl_xor_sync(0xffffffffu, mx0, 2));
        mx1 = fmaxf(mx1, __shfl_xor_sync(0xffffffffu, mx1, 1));
        mx1 = fmaxf(mx1, __shfl_xor_sync(0xffffffffu, mx1, 2));
        const float mn0 = fmaxf(m0, mx0), mn1 = fmaxf(m1, mx1);
        const float al0 = __expf(m0 - mn0), al1 = __expf(m1 - mn1);
        m0 = mn0; m1 = mn1;

        float ls0 = 0.f, ls1 = 0.f;
        #pragma unroll
        for (int nt = 0; nt < 8; nt++) {
            const float p0 = __expf(s[nt][0] - mn0);
            const float p1 = __expf(s[nt][1] - mn0);
            const float p2 = __expf(s[nt][2] - mn1);
            const float p3 = __expf(s[nt][3] - mn1);
            ls0 += p0 + p1; ls1 += p2 + p3;
            const int c0 = nt * 8 + 2 * lr;
            *(float2*)&Pw[lq * KP + c0] =
                make_float2(__uint_as_float(to_tf32(p0)), __uint_as_float(to_tf32(p1)));
            *(float2*)&Pw[(lq + 8) * KP + c0] =
                make_float2(__uint_as_float(to_tf32(p2)), __uint_as_float(to_tf32(p3)));
        }
        ls0 += __shfl_xor_sync(0xffffffffu, ls0, 1);
        ls0 += __shfl_xor_sync(0xffffffffu, ls0, 2);
        ls1 += __shfl_xor_sync(0xffffffffu, ls1, 1);
        ls1 += __shfl_xor_sync(0xffffffffu, ls1, 2);
        l0 = l0 * al0 + ls0;
        l1 = l1 * al1 + ls1;
        #pragma unroll
        for (int dt = 0; dt < 8; dt++) {
            o[dt][0] *= al0; o[dt][1] *= al0;
            o[dt][2] *= al1; o[dt][3] *= al1;
        }
        __syncwarp();      // P visible within warp

        // Phase B: O += P @ V
        #pragma unroll
        for (int kc = 0; kc < 8; kc++) {
            uint32_t pa[4];
            pa[0] = __float_as_uint(Pw[lq * KP + kc * 8 + lr]);
            pa[1] = __float_as_uint(Pw[(lq + 8) * KP + kc * 8 + lr]);
            pa[2] = __float_as_uint(Pw[lq * KP + kc * 8 + lr + 4]);
            pa[3] = __float_as_uint(Pw[(lq + 8) * KP + kc * 8 + lr + 4]);
            #pragma unroll
            for (int dt = 0; dt < 8; dt++) {
                const uint32_t b0 =
                    __float_as_uint(Vs[(kc * 8 + lr) * VP + dt * 8 + lq]);
                const uint32_t b1 =
                    __float_as_uint(Vs[(kc * 8 + lr + 4) * VP + dt * 8 + lq]);
                mma_tf32(o[dt], pa, b0, b1);
            }
        }
        __syncthreads();   // all warps done with Vs and Pw(=Ks) before refill

        if (t + 2 < ntk) issue_tile((t + 2) * 64, cur);
        asm volatile("cp.async.commit_group;" ::: "memory");
    }

    const float inv0 = 1.0f / l0, inv1 = 1.0f / l1;
    const int r0 = q0 + w * 16 + lq, r1 = r0 + 8;
    #pragma unroll
    for (int dt = 0; dt < 8; dt++) {
        const int d = h * 64 + dt * 8 + 2 * lr;
        *(float2*)(g_att + ((size_t)(b * NN + r0)) * CC + d) =
            make_float2(o[dt][0] * inv0, o[dt][1] * inv0);
        *(float2*)(g_att + ((size_t)(b * NN + r1)) * CC + d) =
            make_float2(o[dt][2] * inv1, o[dt][3] * inv1);
    }
}

// ---------------------------------------------------------------------------

extern "C" void kernel_launch(void* const* d_in, const int* in_sizes, int n_in,
                              void* d_out, int out_size)
{
    const float* x      = (const float*)d_in[0];
    const float* mask   = (const float*)d_in[1];
    const float* qkv_w  = (const float*)d_in[2];
    const float* proj_w = (const float*)d_in[3];
    const float* proj_b = (const float*)d_in[4];
    float* out = (float*)d_out;

    const int smem_attn = (2 * KBW + 2 * VBW) * (int)sizeof(float);  // 71,680 B
    cudaFuncSetAttribute(attn_kernel,
                         cudaFuncAttributeMaxDynamicSharedMemorySize, smem_attn);

    const int smem_gemm = 2 * BUFW * (int)sizeof(uint32_t);          // 81,920 B
    cudaFuncSetAttribute(gemm_b<0>,
                         cudaFuncAttributeMaxDynamicSharedMemorySize, smem_gemm);
    cudaFuncSetAttribute(gemm_b<1>,
                         cudaFuncAttributeMaxDynamicSharedMemorySize, smem_gemm);
    cudaFuncSetAttribute(gemm_b<2>,
                         cudaFuncAttributeMaxDynamicSharedMemorySize, smem_gemm);

    compact_kernel<<<BB, 1024>>>(mask);
    gemm_b<0><<<dim3(CC / 128, (BB * NN) / 128), 256, smem_gemm>>>(
        x, qkv_w, nullptr, nullptr);
    gemm_b<1><<<dim3(2 * CC / 128, NN / 128, BB), 256, smem_gemm>>>(
        x, qkv_w + 768 * CC, nullptr, nullptr);
    attn_kernel<<<dim3(NN / 64, HH, BB), 128, smem_attn>>>();
    gemm_b<2><<<dim3(CC / 128, (BB * NN) / 128), 256, smem_gemm>>>(
        nullptr, proj_w, proj_b, out);
}

// round 11
// speedup vs baseline: 1.1549x; 1.1080x over previous
#include <cuda_runtime.h>
#include <cuda_bf16.h>
#include <cstdint>

#define BB   2
#define HH   12
#define NN   2048
#define CC   768
#define DD   64

// Scratch (no allocations allowed)
__device__ float g_q[BB*HH*NN*DD];
__device__ float g_k[BB*HH*NN*DD];
__device__ float g_v[BB*HH*NN*DD];
__device__ float g_att[BB*NN*CC];
__device__ int   g_idx[BB*NN];
__device__ int   g_cnt[BB];

// ---------------------------------------------------------------------------
// mma helpers
// ---------------------------------------------------------------------------
__device__ __forceinline__ void mma_tf32(float* d, const uint32_t* a,
                                         uint32_t b0, uint32_t b1)
{
    asm volatile(
        "mma.sync.aligned.m16n8k8.row.col.f32.tf32.tf32.f32 "
        "{%0,%1,%2,%3},{%4,%5,%6,%7},{%8,%9},{%0,%1,%2,%3};"
        : "+f"(d[0]), "+f"(d[1]), "+f"(d[2]), "+f"(d[3])
        : "r"(a[0]), "r"(a[1]), "r"(a[2]), "r"(a[3]), "r"(b0), "r"(b1));
}

__device__ __forceinline__ void mma_bf16(float* d, const uint32_t* a,
                                         uint32_t b0, uint32_t b1)
{
    asm volatile(
        "mma.sync.aligned.m16n8k16.row.col.f32.bf16.bf16.f32 "
        "{%0,%1,%2,%3},{%4,%5,%6,%7},{%8,%9},{%0,%1,%2,%3};"
        : "+f"(d[0]), "+f"(d[1]), "+f"(d[2]), "+f"(d[3])
        : "r"(a[0]), "r"(a[1]), "r"(a[2]), "r"(a[3]), "r"(b0), "r"(b1));
}

__device__ __forceinline__ uint32_t to_tf32(float f)
{
    uint32_t u;
    asm("cvt.rna.tf32.f32 %0, %1;" : "=r"(u) : "f"(f));
    return u;
}

// split pair (x,y) into packed-bf16 hi word + lo (residual) word
__device__ __forceinline__ void cvt_pair(float x, float y,
                                         uint32_t& hi, uint32_t& lo)
{
    const __nv_bfloat16 hx = __float2bfloat16(x);
    const __nv_bfloat16 hy = __float2bfloat16(y);
    __nv_bfloat162 h; h.x = hx; h.y = hy;
    hi = *reinterpret_cast<uint32_t*>(&h);
    __nv_bfloat162 l;
    l.x = __float2bfloat16(x - __bfloat162float(hx));
    l.y = __float2bfloat16(y - __bfloat162float(hy));
    lo = *reinterpret_cast<uint32_t*>(&l);
}

// ---------------------------------------------------------------------------
// Compaction: per batch, gather indices of visible keys (mask == 0).
// ---------------------------------------------------------------------------
__global__ __launch_bounds__(1024) void compact_kernel(const float* __restrict__ mask)
{
    __shared__ int wsum[32];
    const int b = blockIdx.x;
    const int t = threadIdx.x;
    const int p0 = 2 * t, p1 = 2 * t + 1;
    const int v0 = (mask[b * NN + p0] == 0.0f) ? 1 : 0;
    const int v1 = (mask[b * NN + p1] == 0.0f) ? 1 : 0;
    const int s  = v0 + v1;

    int sc = s;
    #pragma unroll
    for (int o = 1; o < 32; o <<= 1) {
        int n = __shfl_up_sync(0xffffffffu, sc, o);
        if ((t & 31) >= o) sc += n;
    }
    if ((t & 31) == 31) wsum[t >> 5] = sc;
    __syncthreads();
    if (t < 32) {
        int w = wsum[t];
        #pragma unroll
        for (int o = 1; o < 32; o <<= 1) {
            int n = __shfl_up_sync(0xffffffffu, w, o);
            if (t >= o) w += n;
        }
        wsum[t] = w;
    }
    __syncthreads();
    const int excl = (sc - s) + ((t >= 32) ? wsum[(t >> 5) - 1] : 0);
    if (v0) g_idx[b * NN + excl] = p0;
    if (v1) g_idx[b * NN + excl + v0] = p1;
    if (t == 1023) g_cnt[b] = excl + s;
}

// ---------------------------------------------------------------------------
// Merged Q + KV projection GEMM (3xBF16 split), one launch, 576 blocks.
// blocks [0,192): Q proj (M=4096 x N=768);  [192,576): KV proj gathered
// (per-batch compacted M x N=1536).
// ---------------------------------------------------------------------------
#define GP 20
#define BUFW (4*128*GP)

__global__ __launch_bounds__(256) void gemm_qkv(const float* __restrict__ X,
                                                const float* __restrict__ Wq,
                                                const float* __restrict__ Wkv)
{
    extern __shared__ uint32_t su[];

    const int tid = threadIdx.x;
    const int gid = blockIdx.x;
    const bool isQ = (gid < 192);
    int n0, m0, b = 0, cnt = 0;
    const float* W;
    if (isQ) {
        n0 = (gid % 6) * 128;
        m0 = (gid / 6) * 128;
        W  = Wq;
    } else {
        const int g2 = gid - 192;
        n0 = (g2 % 12) * 128;
        m0 = ((g2 / 12) & 15) * 128;
        b  = g2 / 192;
        cnt = g_cnt[b];
        if (m0 >= cnt) return;
        W  = Wkv;
    }

    int lrow[4], lw[4];
    size_t a_off[4], b_off[4];
    #pragma unroll
    for (int p = 0; p < 4; p++) {
        const int f = tid + p * 256;
        lrow[p] = f >> 3;
        lw[p]   = (f & 7) * 2;
        const int col4 = (f & 7) * 4;
        if (!isQ) {
            const int mrow = m0 + lrow[p];
            const int src  = (mrow < cnt) ? g_idx[b * NN + mrow] : 0;
            a_off[p] = ((size_t)(b * NN + src)) * CC + col4;
        } else {
            a_off[p] = (size_t)(m0 + lrow[p]) * CC + col4;
        }
        b_off[p] = (size_t)(n0 + lrow[p]) * CC + col4;
    }

    const int w = tid >> 5, lane = tid & 31;
    const int wm0 = (w >> 2) * 64;
    const int wn0 = (w & 3) * 32;
    const int lq = lane >> 2;
    const int lr = lane & 3;

    float acc[4][4][4] = {};

    float4 pa[4], pb[4];
    #pragma unroll
    for (int p = 0; p < 4; p++) {
        pa[p] = *(const float4*)(X + a_off[p]);
        pb[p] = *(const float4*)(W + b_off[p]);
    }

    int buf = 0;
    const int NK = CC / 32;
    for (int kt = 0; kt < NK; kt++) {
        uint32_t* AH = su + buf * BUFW;
        uint32_t* AL = AH + 128 * GP;
        uint32_t* BH = AL + 128 * GP;
        uint32_t* BL = BH + 128 * GP;

        #pragma unroll
        for (int p = 0; p < 4; p++) {
            uint32_t h0, l0, h1, l1;
            cvt_pair(pa[p].x, pa[p].y, h0, l0);
            cvt_pair(pa[p].z, pa[p].w, h1, l1);
            *(uint2*)&AH[lrow[p] * GP + lw[p]] = make_uint2(h0, h1);
            *(uint2*)&AL[lrow[p] * GP + lw[p]] = make_uint2(l0, l1);
            cvt_pair(pb[p].x, pb[p].y, h0, l0);
            cvt_pair(pb[p].z, pb[p].w, h1, l1);
            *(uint2*)&BH[lrow[p] * GP + lw[p]] = make_uint2(h0, h1);
            *(uint2*)&BL[lrow[p] * GP + lw[p]] = make_uint2(l0, l1);
        }
        __syncthreads();

        if (kt + 1 < NK) {
            #pragma unroll
            for (int p = 0; p < 4; p++) {
                pa[p] = *(const float4*)(X + a_off[p] + (kt + 1) * 32);
                pb[p] = *(const float4*)(W + b_off[p] + (kt + 1) * 32);
            }
        }

        #pragma unroll
        for (int kb = 0; kb < 2; kb++) {
            const int wb = kb * 8;
            uint32_t aH[4][4], aL[4][4];
            #pragma unroll
            for (int i = 0; i < 4; i++) {
                const int r = wm0 + i * 16 + lq;
                aH[i][0] = AH[r * GP + wb + lr];
                aH[i][1] = AH[(r + 8) * GP + wb + lr];
                aH[i][2] = AH[r * GP + wb + 4 + lr];
                aH[i][3] = AH[(r + 8) * GP + wb + 4 + lr];
                aL[i][0] = AL[r * GP + wb + lr];
                aL[i][1] = AL[(r + 8) * GP + wb + lr];
                aL[i][2] = AL[r * GP + wb + 4 + lr];
                aL[i][3] = AL[(r + 8) * GP + wb + 4 + lr];
            }
            uint32_t bH[4][2], bL[4][2];
            #pragma unroll
            for (int j = 0; j < 4; j++) {
                const int n = wn0 + j * 8 + lq;
                bH[j][0] = BH[n * GP + wb + lr];
                bH[j][1] = BH[n * GP + wb + 4 + lr];
                bL[j][0] = BL[n * GP + wb + lr];
                bL[j][1] = BL[n * GP + wb + 4 + lr];
            }
            #pragma unroll
            for (int i = 0; i < 4; i++)
                #pragma unroll
                for (int j = 0; j < 4; j++) {
                    mma_bf16(acc[i][j], aH[i], bH[j][0], bH[j][1]);
                    mma_bf16(acc[i][j], aH[i], bL[j][0], bL[j][1]);
                    mma_bf16(acc[i][j], aL[i], bH[j][0], bH[j][1]);
                }
        }
        __syncthreads();
        buf ^= 1;
    }

    #pragma unroll
    for (int i = 0; i < 4; i++) {
        #pragma unroll
        for (int half = 0; half < 2; half++) {
            const int m = m0 + wm0 + i * 16 + lq + half * 8;
            if (!isQ && m >= cnt) continue;
            #pragma unroll
            for (int j = 0; j < 4; j++) {
                const int c  = n0 + wn0 + j * 8 + 2 * lr;
                const float v0 = acc[i][j][half * 2];
                const float v1 = acc[i][j][half * 2 + 1];
                if (isQ) {
                    const int bpos = m >> 11, nn = m & 2047;
                    const int h = c >> 6, d = c & 63;
                    *(float2*)&g_q[(((size_t)bpos * HH + h) * NN + nn) * DD + d] =
                        make_float2(v0, v1);
                } else {
                    const bool isv = (c >= 768);
                    const int cc2 = isv ? (c - 768) : c;
                    const int h = cc2 >> 6, d = cc2 & 63;
                    float* dst = isv ? g_v : g_k;
                    *(float2*)&dst[(((size_t)b * HH + h) * NN + m) * DD + d] =
                        make_float2(v0, v1);
                }
            }
        }
    }
}

// ---------------------------------------------------------------------------
// Output projection GEMM (3xBF16 split), unchanged mainloop.
// ---------------------------------------------------------------------------
__global__ __launch_bounds__(256) void gemm_out(const float* __restrict__ W,
                                                const float* __restrict__ bias,
                                                float* __restrict__ out)
{
    extern __shared__ uint32_t su[];

    const int tid = threadIdx.x;
    const int n0 = blockIdx.x * 128;
    const int m0 = blockIdx.y * 128;

    int lrow[4], lw[4];
    size_t a_off[4], b_off[4];
    #pragma unroll
    for (int p = 0; p < 4; p++) {
        const int f = tid + p * 256;
        lrow[p] = f >> 3;
        lw[p]   = (f & 7) * 2;
        const int col4 = (f & 7) * 4;
        a_off[p] = (size_t)(m0 + lrow[p]) * CC + col4;
        b_off[p] = (size_t)(n0 + lrow[p]) * CC + col4;
    }

    const int w = tid >> 5, lane = tid & 31;
    const int wm0 = (w >> 2) * 64;
    const int wn0 = (w & 3) * 32;
    const int lq = lane >> 2;
    const int lr = lane & 3;

    float acc[4][4][4] = {};

    float4 pa[4], pb[4];
    #pragma unroll
    for (int p = 0; p < 4; p++) {
        pa[p] = *(const float4*)(g_att + a_off[p]);
        pb[p] = *(const float4*)(W + b_off[p]);
    }

    int buf = 0;
    const int NK = CC / 32;
    for (int kt = 0; kt < NK; kt++) {
        uint32_t* AH = su + buf * BUFW;
        uint32_t* AL = AH + 128 * GP;
        uint32_t* BH = AL + 128 * GP;
        uint32_t* BL = BH + 128 * GP;

        #pragma unroll
        for (int p = 0; p < 4; p++) {
            uint32_t h0, l0, h1, l1;
            cvt_pair(pa[p].x, pa[p].y, h0, l0);
            cvt_pair(pa[p].z, pa[p].w, h1, l1);
            *(uint2*)&AH[lrow[p] * GP + lw[p]] = make_uint2(h0, h1);
            *(uint2*)&AL[lrow[p] * GP + lw[p]] = make_uint2(l0, l1);
            cvt_pair(pb[p].x, pb[p].y, h0, l0);
            cvt_pair(pb[p].z, pb[p].w, h1, l1);
            *(uint2*)&BH[lrow[p] * GP + lw[p]] = make_uint2(h0, h1);
            *(uint2*)&BL[lrow[p] * GP + lw[p]] = make_uint2(l0, l1);
        }
        __syncthreads();

        if (kt + 1 < NK) {
            #pragma unroll
            for (int p = 0; p < 4; p++) {
                pa[p] = *(const float4*)(g_att + a_off[p] + (kt + 1) * 32);
                pb[p] = *(const float4*)(W + b_off[p] + (kt + 1) * 32);
            }
        }

        #pragma unroll
        for (int kb = 0; kb < 2; kb++) {
            const int wb = kb * 8;
            uint32_t aH[4][4], aL[4][4];
            #pragma unroll
            for (int i = 0; i < 4; i++) {
                const int r = wm0 + i * 16 + lq;
                aH[i][0] = AH[r * GP + wb + lr];
                aH[i][1] = AH[(r + 8) * GP + wb + lr];
                aH[i][2] = AH[r * GP + wb + 4 + lr];
                aH[i][3] = AH[(r + 8) * GP + wb + 4 + lr];
                aL[i][0] = AL[r * GP + wb + lr];
                aL[i][1] = AL[(r + 8) * GP + wb + lr];
                aL[i][2] = AL[r * GP + wb + 4 + lr];
                aL[i][3] = AL[(r + 8) * GP + wb + 4 + lr];
            }
            uint32_t bH[4][2], bL[4][2];
            #pragma unroll
            for (int j = 0; j < 4; j++) {
                const int n = wn0 + j * 8 + lq;
                bH[j][0] = BH[n * GP + wb + lr];
                bH[j][1] = BH[n * GP + wb + 4 + lr];
                bL[j][0] = BL[n * GP + wb + lr];
                bL[j][1] = BL[n * GP + wb + 4 + lr];
            }
            #pragma unroll
            for (int i = 0; i < 4; i++)
                #pragma unroll
                for (int j = 0; j < 4; j++) {
                    mma_bf16(acc[i][j], aH[i], bH[j][0], bH[j][1]);
                    mma_bf16(acc[i][j], aH[i], bL[j][0], bL[j][1]);
                    mma_bf16(acc[i][j], aL[i], bH[j][0], bH[j][1]);
                }
        }
        __syncthreads();
        buf ^= 1;
    }

    #pragma unroll
    for (int i = 0; i < 4; i++) {
        #pragma unroll
        for (int half = 0; half < 2; half++) {
            const int m = m0 + wm0 + i * 16 + lq + half * 8;
            #pragma unroll
            for (int j = 0; j < 4; j++) {
                const int c = n0 + wn0 + j * 8 + 2 * lr;
                *(float2*)&out[(size_t)m * CC + c] =
                    make_float2(acc[i][j][half * 2] + bias[c],
                                acc[i][j][half * 2 + 1] + bias[c + 1]);
            }
        }
    }
}

// ---------------------------------------------------------------------------
// Flash attention, tf32 mma.sync, cp.async double-buffered K/V,
// SHUFFLE-converted P (C-frag -> A-frag, quad-local permutation).
// No P smem traffic; 2 block syncs per tile. Bit-identical numerics.
// ---------------------------------------------------------------------------
#define KP 68
#define VP 72
#define KBW (64*KP)
#define VBW (64*VP)

__global__ __launch_bounds__(128) void attn_kernel()
{
    extern __shared__ float sm[];
    float* KB = sm;              // 2 x 64 x KP
    float* VB = sm + 2 * KBW;    // 2 x 64 x VP

    const int tid  = threadIdx.x;
    const int w    = tid >> 5, lane = tid & 31;
    const int lq   = lane >> 2;
    const int lr   = lane & 3;
    const int q0   = blockIdx.x * 64;
    const int h    = blockIdx.y;
    const int b    = blockIdx.z;
    const int cnt  = g_cnt[b];
    const size_t base = ((size_t)(b * HH + h)) * NN * DD;

    // ---- Stage Q into KB[0], extract loop-invariant pre-scaled A-fragments
    for (int e = tid * 4; e < 64 * 64; e += 512) {
        const int r = e >> 6, c = e & 63;
        *(float4*)(KB + r * KP + c) =
            *(const float4*)(g_q + base + (size_t)(q0 + r) * DD + c);
    }
    __syncthreads();
    uint32_t qa[8][4];
    #pragma unroll
    for (int kc = 0; kc < 8; kc++) {
        const int r0 = w * 16 + lq;
        qa[kc][0] = to_tf32(KB[r0 * KP + kc * 8 + lr] * 0.125f);
        qa[kc][1] = to_tf32(KB[(r0 + 8) * KP + kc * 8 + lr] * 0.125f);
        qa[kc][2] = to_tf32(KB[r0 * KP + kc * 8 + lr + 4] * 0.125f);
        qa[kc][3] = to_tf32(KB[(r0 + 8) * KP + kc * 8 + lr + 4] * 0.125f);
    }
    __syncthreads();

    // ---- cp.async tile loader (zero-fill past cnt) ----
    auto issue_tile = [&](int kt, int bufi) {
        float* Kb = KB + bufi * KBW;
        float* Vb = VB + bufi * VBW;
        #pragma unroll
        for (int e = tid * 4; e < 64 * 64; e += 512) {
            const int r = e >> 6, c = e & 63;
            const int gr = kt + r;
            const int sz = (gr < cnt) ? 16 : 0;
            const int grc = (gr < NN) ? gr : (NN - 1);
            const float* ksrc = g_k + base + (size_t)grc * DD + c;
            const float* vsrc = g_v + base + (size_t)grc * DD + c;
            const uint32_t ka = (uint32_t)__cvta_generic_to_shared(Kb + r * KP + c);
            const uint32_t va = (uint32_t)__cvta_generic_to_shared(Vb + r * VP + c);
            asm volatile("cp.async.ca.shared.global [%0], [%1], 16, %2;"
                         :: "r"(ka), "l"(ksrc), "r"(sz));
            asm volatile("cp.async.ca.shared.global [%0], [%1], 16, %2;"
                         :: "r"(va), "l"(vsrc), "r"(sz));
        }
    };

    const int ntk = (cnt + 63) >> 6;
    issue_tile(0, 0);
    asm volatile("cp.async.commit_group;" ::: "memory");
    if (ntk > 1) issue_tile(64, 1);
    asm volatile("cp.async.commit_group;" ::: "memory");

    float o[8][4] = {};
    float m0 = -1e30f, m1 = -1e30f, l0 = 0.f, l1 = 0.f;

    for (int t = 0; t < ntk; t++) {
        asm volatile("cp.async.wait_group 1;" ::: "memory");
        __syncthreads();
        const int  kt = t * 64;
        const int  cur = t & 1;
        float* Ks = KB + cur * KBW;
        float* Vs = VB + cur * VBW;

        // Phase A: S = Q @ K^T
        float s[8][4];
        #pragma unroll
        for (int nt = 0; nt < 8; nt++) {
            s[nt][0] = s[nt][1] = s[nt][2] = s[nt][3] = 0.f;
            #pragma unroll
            for (int kc = 0; kc < 8; kc++) {
                const uint32_t b0 =
                    __float_as_uint(Ks[(nt * 8 + lq) * KP + kc * 8 + lr]);
                const uint32_t b1 =
                    __float_as_uint(Ks[(nt * 8 + lq) * KP + kc * 8 + lr + 4]);
                mma_tf32(s[nt], qa[kc], b0, b1);
            }
        }

        // Online softmax (identical ordering); result left in s as tf32 bits
        float mx0 = -1e30f, mx1 = -1e30f;
        #pragma unroll
        for (int nt = 0; nt < 8; nt++) {
            const int col = kt + nt * 8 + 2 * lr;
            if (col >= cnt)     { s[nt][0] = -1e30f; s[nt][2] = -1e30f; }
            if (col + 1 >= cnt) { s[nt][1] = -1e30f; s[nt][3] = -1e30f; }
            mx0 = fmaxf(mx0, fmaxf(s[nt][0], s[nt][1]));
            mx1 = fmaxf(mx1, fmaxf(s[nt][2], s[nt][3]));
        }
        mx0 = fmaxf(mx0, __shfl_xor_sync(0xffffffffu, mx0, 1));
        mx0 = fmaxf(mx0, __shfl_xor_sync(0xffffffffu, mx0, 2));
        mx1 = fmaxf(mx1, __shfl_xor_sync(0xffffffffu, mx1, 1));
        mx1 = fmaxf(mx1, __shfl_xor_sync(0xffffffffu, mx1, 2));
        const float mn0 = fmaxf(m0, mx0), mn1 = fmaxf(m1, mx1);
        const float al0 = __expf(m0 - mn0), al1 = __expf(m1 - mn1);
        m0 = mn0; m1 = mn1;

        float ls0 = 0.f, ls1 = 0.f;
        #pragma unroll
        for (int nt = 0; nt < 8; nt++) {
            const float p0 = __expf(s[nt][0] - mn0);
            const float p1 = __expf(s[nt][1] - mn0);
            const float p2 = __expf(s[nt][2] - mn1);
            const float p3 = __expf(s[nt][3] - mn1);
            ls0 += p0 + p1; ls1 += p2 + p3;
            s[nt][0] = __uint_as_float(to_tf32(p0));
            s[nt][1] = __uint_as_float(to_tf32(p1));
            s[nt][2] = __uint_as_float(to_tf32(p2));
            s[nt][3] = __uint_as_float(to_tf32(p3));
        }
        ls0 += __shfl_xor_sync(0xffffffffu, ls0, 1);
        ls0 += __shfl_xor_sync(0xffffffffu, ls0, 2);
        ls1 += __shfl_xor_sync(0xffffffffu, ls1, 1);
        ls1 += __shfl_xor_sync(0xffffffffu, ls1, 2);
        l0 = l0 * al0 + ls0;
        l1 = l1 * al1 + ls1;
        #pragma unroll
        for (int dt = 0; dt < 8; dt++) {
            o[dt][0] *= al0; o[dt][1] *= al0;
            o[dt][2] *= al1; o[dt][3] *= al1;
        }

        // Phase B: O += P @ V, P C-frag -> A-frag via quad-local shuffles.
        // P(row, col kc*8+j) owner: lane 4*(row%8)+(j>>1), reg (j&1)+2*(row>=8)
        const int src0 = (lane & 28) | (lr >> 1);
        const int src2 = src0 | 2;
        #pragma unroll
        for (int kc = 0; kc < 8; kc++) {
            const uint32_t P0 = __float_as_uint(s[kc][0]);
            const uint32_t P1 = __float_as_uint(s[kc][1]);
            const uint32_t P2 = __float_as_uint(s[kc][2]);
            const uint32_t P3 = __float_as_uint(s[kc][3]);
            const uint32_t u0 = __shfl_sync(0xffffffffu, P0, src0);
            const uint32_t u1 = __shfl_sync(0xffffffffu, P1, src0);
            const uint32_t u2 = __shfl_sync(0xffffffffu, P2, src0);
            const uint32_t u3 = __shfl_sync(0xffffffffu, P3, src0);
            const uint32_t v0 = __shfl_sync(0xffffffffu, P0, src2);
            const uint32_t v1 = __shfl_sync(0xffffffffu, P1, src2);
            const uint32_t v2 = __shfl_sync(0xffffffffu, P2, src2);
            const uint32_t v3 = __shfl_sync(0xffffffffu, P3, src2);
            uint32_t pa[4];
            pa[0] = (lr & 1) ? u1 : u0;
            pa[1] = (lr & 1) ? u3 : u2;
            pa[2] = (lr & 1) ? v1 : v0;
            pa[3] = (lr & 1) ? v3 : v2;
            #pragma unroll
            for (int dt = 0; dt < 8; dt++) {
                const uint32_t b0 =
                    __float_as_uint(Vs[(kc * 8 + lr) * VP + dt * 8 + lq]);
                const uint32_t b1 =
                    __float_as_uint(Vs[(kc * 8 + lr + 4) * VP + dt * 8 + lq]);
                mma_tf32(o[dt], pa, b0, b1);
            }
        }
        __syncthreads();   // all warps done with Ks/Vs before refill

        if (t + 2 < ntk) issue_tile((t + 2) * 64, cur);
        asm volatile("cp.async.commit_group;" ::: "memory");
    }

    const float inv0 = 1.0f / l0, inv1 = 1.0f / l1;
    const int r0 = q0 + w * 16 + lq, r1 = r0 + 8;
    #pragma unroll
    for (int dt = 0; dt < 8; dt++) {
        const int d = h * 64 + dt * 8 + 2 * lr;
        *(float2*)(g_att + ((size_t)(b * NN + r0)) * CC + d) =
            make_float2(o[dt][0] * inv0, o[dt][1] * inv0);
        *(float2*)(g_att + ((size_t)(b * NN + r1)) * CC + d) =
            make_float2(o[dt][2] * inv1, o[dt][3] * inv1);
    }
}

// ---------------------------------------------------------------------------

extern "C" void kernel_launch(void* const* d_in, const int* in_sizes, int n_in,
                              void* d_out, int out_size)
{
    const float* x      = (const float*)d_in[0];
    const float* mask   = (const float*)d_in[1];
    const float* qkv_w  = (const float*)d_in[2];
    const float* proj_w = (const float*)d_in[3];
    const float* proj_b = (const float*)d_in[4];
    float* out = (float*)d_out;

    const int smem_attn = (2 * KBW + 2 * VBW) * (int)sizeof(float);  // 71,680 B
    cudaFuncSetAttribute(attn_kernel,
                         cudaFuncAttributeMaxDynamicSharedMemorySize, smem_attn);

    const int smem_gemm = 2 * BUFW * (int)sizeof(uint32_t);          // 81,920 B
    cudaFuncSetAttribute(gemm_qkv,
                         cudaFuncAttributeMaxDynamicSharedMemorySize, smem_gemm);
    cudaFuncSetAttribute(gemm_out,
                         cudaFuncAttributeMaxDynamicSharedMemorySize, smem_gemm);

    compact_kernel<<<BB, 1024>>>(mask);
    gemm_qkv<<<576, 256, smem_gemm>>>(x, qkv_w, qkv_w + 768 * CC);
    attn_kernel<<<dim3(NN / 64, HH, BB), 128, smem_attn>>>();
    gemm_out<<<dim3(CC / 128, (BB * NN) / 128), 256, smem_gemm>>>(proj_w, proj_b, out);
}

// round 13
// speedup vs baseline: 1.1628x; 1.0068x over previous
#include <cuda_runtime.h>
#include <cuda_bf16.h>
#include <cstdint>

#define BB   2
#define HH   12
#define NN   2048
#define CC   768
#define DD   64

// Scratch (no allocations allowed)
__device__ float g_q[BB*HH*NN*DD];
__device__ float g_k[BB*HH*NN*DD];
__device__ float g_v[BB*HH*NN*DD];
__device__ float g_att[BB*NN*CC];
__device__ int   g_idx[BB*NN];
__device__ int   g_cnt[BB];

// ---------------------------------------------------------------------------
// mma helpers
// ---------------------------------------------------------------------------
__device__ __forceinline__ void mma_tf32(float* d, const uint32_t* a,
                                         uint32_t b0, uint32_t b1)
{
    asm volatile(
        "mma.sync.aligned.m16n8k8.row.col.f32.tf32.tf32.f32 "
        "{%0,%1,%2,%3},{%4,%5,%6,%7},{%8,%9},{%0,%1,%2,%3};"
        : "+f"(d[0]), "+f"(d[1]), "+f"(d[2]), "+f"(d[3])
        : "r"(a[0]), "r"(a[1]), "r"(a[2]), "r"(a[3]), "r"(b0), "r"(b1));
}

__device__ __forceinline__ void mma_bf16(float* d, const uint32_t* a,
                                         uint32_t b0, uint32_t b1)
{
    asm volatile(
        "mma.sync.aligned.m16n8k16.row.col.f32.bf16.bf16.f32 "
        "{%0,%1,%2,%3},{%4,%5,%6,%7},{%8,%9},{%0,%1,%2,%3};"
        : "+f"(d[0]), "+f"(d[1]), "+f"(d[2]), "+f"(d[3])
        : "r"(a[0]), "r"(a[1]), "r"(a[2]), "r"(a[3]), "r"(b0), "r"(b1));
}

__device__ __forceinline__ uint32_t to_tf32(float f)
{
    uint32_t u;
    asm("cvt.rna.tf32.f32 %0, %1;" : "=r"(u) : "f"(f));
    return u;
}

// split pair (x,y) into packed-bf16 hi word + lo (residual) word
__device__ __forceinline__ void cvt_pair(float x, float y,
                                         uint32_t& hi, uint32_t& lo)
{
    const __nv_bfloat16 hx = __float2bfloat16(x);
    const __nv_bfloat16 hy = __float2bfloat16(y);
    __nv_bfloat162 h; h.x = hx; h.y = hy;
    hi = *reinterpret_cast<uint32_t*>(&h);
    __nv_bfloat162 l;
    l.x = __float2bfloat16(x - __bfloat162float(hx));
    l.y = __float2bfloat16(y - __bfloat162float(hy));
    lo = *reinterpret_cast<uint32_t*>(&l);
}

// ---------------------------------------------------------------------------
// Compaction: per batch, gather indices of visible keys (mask == 0).
// ---------------------------------------------------------------------------
__global__ __launch_bounds__(1024) void compact_kernel(const float* __restrict__ mask)
{
    __shared__ int wsum[32];
    const int b = blockIdx.x;
    const int t = threadIdx.x;
    const int p0 = 2 * t, p1 = 2 * t + 1;
    const int v0 = (mask[b * NN + p0] == 0.0f) ? 1 : 0;
    const int v1 = (mask[b * NN + p1] == 0.0f) ? 1 : 0;
    const int s  = v0 + v1;

    int sc = s;
    #pragma unroll
    for (int o = 1; o < 32; o <<= 1) {
        int n = __shfl_up_sync(0xffffffffu, sc, o);
        if ((t & 31) >= o) sc += n;
    }
    if ((t & 31) == 31) wsum[t >> 5] = sc;
    __syncthreads();
    if (t < 32) {
        int w = wsum[t];
        #pragma unroll
        for (int o = 1; o < 32; o <<= 1) {
            int n = __shfl_up_sync(0xffffffffu, w, o);
            if (t >= o) w += n;
        }
        wsum[t] = w;
    }
    __syncthreads();
    const int excl = (sc - s) + ((t >= 32) ? wsum[(t >> 5) - 1] : 0);
    if (v0) g_idx[b * NN + excl] = p0;
    if (v1) g_idx[b * NN + excl + v0] = p1;
    if (t == 1023) g_cnt[b] = excl + s;
}

// ---------------------------------------------------------------------------
// Tensor-core GEMM core, 3xBF16 split, block tile 128(m) x 64(n), k-step 32,
// double-buffered smem, 8 warps (4m x 2n, 32x32 warp tiles), 2 blocks/SM.
// ---------------------------------------------------------------------------
#define GPW 20
#define ABW (128*GPW)            // words per A array (H or L)
#define BBW (64*GPW)             // words per B array
#define STGW (2*ABW + 2*BBW)     // 7680 words per stage buffer

// Computes acc for tile (Ap row-gathered optionally) -- shared by all modes.
// Returns via acc[2][4][4].
struct TileCtx {
    int arow[4]; int aw[4]; size_t a_off[4];
    int brow[2]; int bw[2]; size_t b_off[2];
    int wm0, wn0, lq, lr;
};

__device__ __forceinline__ void gemm_core(const float* __restrict__ Ap,
                                          const float* __restrict__ W,
                                          uint32_t* su, TileCtx& cx,
                                          float acc[2][4][4])
{
    const int tid = threadIdx.x;
    float4 pa[4], pb[2];
    #pragma unroll
    for (int p = 0; p < 4; p++) pa[p] = *(const float4*)(Ap + cx.a_off[p]);
    #pragma unroll
    for (int p = 0; p < 2; p++) pb[p] = *(const float4*)(W + cx.b_off[p]);

    int buf = 0;
    const int NK = CC / 32;
    for (int kt = 0; kt < NK; kt++) {
        uint32_t* AH = su + buf * STGW;
        uint32_t* AL = AH + ABW;
        uint32_t* BH = AL + ABW;
        uint32_t* BL = BH + BBW;

        #pragma unroll
        for (int p = 0; p < 4; p++) {
            uint32_t h0, l0, h1, l1;
            cvt_pair(pa[p].x, pa[p].y, h0, l0);
            cvt_pair(pa[p].z, pa[p].w, h1, l1);
            *(uint2*)&AH[cx.arow[p] * GPW + cx.aw[p]] = make_uint2(h0, h1);
            *(uint2*)&AL[cx.arow[p] * GPW + cx.aw[p]] = make_uint2(l0, l1);
        }
        #pragma unroll
        for (int p = 0; p < 2; p++) {
            uint32_t h0, l0, h1, l1;
            cvt_pair(pb[p].x, pb[p].y, h0, l0);
            cvt_pair(pb[p].z, pb[p].w, h1, l1);
            *(uint2*)&BH[cx.brow[p] * GPW + cx.bw[p]] = make_uint2(h0, h1);
            *(uint2*)&BL[cx.brow[p] * GPW + cx.bw[p]] = make_uint2(l0, l1);
        }
        __syncthreads();

        if (kt + 1 < NK) {
            #pragma unroll
            for (int p = 0; p < 4; p++)
                pa[p] = *(const float4*)(Ap + cx.a_off[p] + (kt + 1) * 32);
            #pragma unroll
            for (int p = 0; p < 2; p++)
                pb[p] = *(const float4*)(W + cx.b_off[p] + (kt + 1) * 32);
        }

        #pragma unroll
        for (int kb = 0; kb < 2; kb++) {
            const int wb = kb * 8;
            uint32_t aH[2][4], aL[2][4];
            #pragma unroll
            for (int i = 0; i < 2; i++) {
                const int r = cx.wm0 + i * 16 + cx.lq;
                aH[i][0] = AH[r * GPW + wb + cx.lr];
                aH[i][1] = AH[(r + 8) * GPW + wb + cx.lr];
                aH[i][2] = AH[r * GPW + wb + 4 + cx.lr];
                aH[i][3] = AH[(r + 8) * GPW + wb + 4 + cx.lr];
                aL[i][0] = AL[r * GPW + wb + cx.lr];
                aL[i][1] = AL[(r + 8) * GPW + wb + cx.lr];
                aL[i][2] = AL[r * GPW + wb + 4 + cx.lr];
                aL[i][3] = AL[(r + 8) * GPW + wb + 4 + cx.lr];
            }
            uint32_t bH[4][2], bL[4][2];
            #pragma unroll
            for (int j = 0; j < 4; j++) {
                const int n = cx.wn0 + j * 8 + cx.lq;
                bH[j][0] = BH[n * GPW + wb + cx.lr];
                bH[j][1] = BH[n * GPW + wb + 4 + cx.lr];
                bL[j][0] = BL[n * GPW + wb + cx.lr];
                bL[j][1] = BL[n * GPW + wb + 4 + cx.lr];
            }
            #pragma unroll
            for (int i = 0; i < 2; i++)
                #pragma unroll
                for (int j = 0; j < 4; j++) {
                    mma_bf16(acc[i][j], aH[i], bH[j][0], bH[j][1]);
                    mma_bf16(acc[i][j], aH[i], bL[j][0], bL[j][1]);
                    mma_bf16(acc[i][j], aL[i], bH[j][0], bH[j][1]);
                }
        }
        __syncthreads();
        buf ^= 1;
    }
    (void)tid;
}

__device__ __forceinline__ void init_ctx(TileCtx& cx, int m0, int n0,
                                         bool gather, int b, int cnt)
{
    const int tid = threadIdx.x;
    #pragma unroll
    for (int p = 0; p < 4; p++) {
        const int f = tid + p * 256;
        cx.arow[p] = f >> 3;
        cx.aw[p]   = (f & 7) * 2;
        const int col4 = (f & 7) * 4;
        if (gather) {
            const int mrow = m0 + cx.arow[p];
            const int src  = (mrow < cnt) ? g_idx[b * NN + mrow] : 0;
            cx.a_off[p] = ((size_t)(b * NN + src)) * CC + col4;
        } else {
            cx.a_off[p] = (size_t)(m0 + cx.arow[p]) * CC + col4;
        }
    }
    #pragma unroll
    for (int p = 0; p < 2; p++) {
        const int f = tid + p * 256;
        cx.brow[p] = f >> 3;
        cx.bw[p]   = (f & 7) * 2;
        cx.b_off[p] = (size_t)(n0 + cx.brow[p]) * CC + (f & 7) * 4;
    }
    const int w = tid >> 5, lane = tid & 31;
    cx.wm0 = (w >> 1) * 32;
    cx.wn0 = (w & 1) * 32;
    cx.lq  = lane >> 2;
    cx.lr  = lane & 3;
}

// ---------------------------------------------------------------------------
// Merged Q + KV projection (one launch).
// gid < 384:  Q proj, n0=(gid%12)*64, m0=(gid/12)*128
// gid >= 384: KV proj gathered, n0=(g2%24)*64, m0=((g2/24)&15)*128, b=g2/384
// ---------------------------------------------------------------------------
__global__ __launch_bounds__(256, 2) void gemm_qkv(const float* __restrict__ X,
                                                   const float* __restrict__ Wq,
                                                   const float* __restrict__ Wkv)
{
    extern __shared__ uint32_t su[];
    const int gid = blockIdx.x;
    const bool isQ = (gid < 384);
    int n0, m0, b = 0, cnt = 0;
    const float* W;
    if (isQ) {
        n0 = (gid % 12) * 64;
        m0 = (gid / 12) * 128;
        W  = Wq;
    } else {
        const int g2 = gid - 384;
        n0 = (g2 % 24) * 64;
        m0 = ((g2 / 24) & 15) * 128;
        b  = g2 / 384;
        cnt = g_cnt[b];
        if (m0 >= cnt) return;
        W  = Wkv;
    }

    TileCtx cx;
    init_ctx(cx, m0, n0, !isQ, b, cnt);
    float acc[2][4][4] = {};
    gemm_core(X, W, su, cx, acc);

    #pragma unroll
    for (int i = 0; i < 2; i++) {
        #pragma unroll
        for (int half = 0; half < 2; half++) {
            const int m = m0 + cx.wm0 + i * 16 + cx.lq + half * 8;
            if (!isQ && m >= cnt) continue;
            #pragma unroll
            for (int j = 0; j < 4; j++) {
                const int c  = n0 + cx.wn0 + j * 8 + 2 * cx.lr;
                const float v0 = acc[i][j][half * 2];
                const float v1 = acc[i][j][half * 2 + 1];
                if (isQ) {
                    const int bpos = m >> 11, nn = m & 2047;
                    const int h = c >> 6, d = c & 63;
                    *(float2*)&g_q[(((size_t)bpos * HH + h) * NN + nn) * DD + d] =
                        make_float2(v0, v1);
                } else {
                    const bool isv = (c >= 768);
                    const int cc2 = isv ? (c - 768) : c;
                    const int h = cc2 >> 6, d = cc2 & 63;
                    float* dst = isv ? g_v : g_k;
                    *(float2*)&dst[(((size_t)b * HH + h) * NN + m) * DD + d] =
                        make_float2(v0, v1);
                }
            }
        }
    }
}

// ---------------------------------------------------------------------------
// Output projection GEMM (+bias).
// ---------------------------------------------------------------------------
__global__ __launch_bounds__(256, 2) void gemm_out(const float* __restrict__ W,
                                                   const float* __restrict__ bias,
                                                   float* __restrict__ out)
{
    extern __shared__ uint32_t su[];
    const int n0 = blockIdx.x * 64;
    const int m0 = blockIdx.y * 128;

    TileCtx cx;
    init_ctx(cx, m0, n0, false, 0, 0);
    float acc[2][4][4] = {};
    gemm_core(g_att, W, su, cx, acc);

    #pragma unroll
    for (int i = 0; i < 2; i++) {
        #pragma unroll
        for (int half = 0; half < 2; half++) {
            const int m = m0 + cx.wm0 + i * 16 + cx.lq + half * 8;
            #pragma unroll
            for (int j = 0; j < 4; j++) {
                const int c = n0 + cx.wn0 + j * 8 + 2 * cx.lr;
                *(float2*)&out[(size_t)m * CC + c] =
                    make_float2(acc[i][j][half * 2] + bias[c],
                                acc[i][j][half * 2 + 1] + bias[c + 1]);
            }
        }
    }
}

// ---------------------------------------------------------------------------
// Flash attention, tf32 mma.sync, cp.async double-buffered K/V,
// shuffle-converted P. Unchanged from R11 (bit-identical numerics).
// ---------------------------------------------------------------------------
#define KP 68
#define VP 72
#define KBW (64*KP)
#define VBW (64*VP)

__global__ __launch_bounds__(128) void attn_kernel()
{
    extern __shared__ float sm[];
    float* KB = sm;              // 2 x 64 x KP
    float* VB = sm + 2 * KBW;    // 2 x 64 x VP

    const int tid  = threadIdx.x;
    const int w    = tid >> 5, lane = tid & 31;
    const int lq   = lane >> 2;
    const int lr   = lane & 3;
    const int q0   = blockIdx.x * 64;
    const int h    = blockIdx.y;
    const int b    = blockIdx.z;
    const int cnt  = g_cnt[b];
    const size_t base = ((size_t)(b * HH + h)) * NN * DD;

    for (int e = tid * 4; e < 64 * 64; e += 512) {
        const int r = e >> 6, c = e & 63;
        *(float4*)(KB + r * KP + c) =
            *(const float4*)(g_q + base + (size_t)(q0 + r) * DD + c);
    }
    __syncthreads();
    uint32_t qa[8][4];
    #pragma unroll
    for (int kc = 0; kc < 8; kc++) {
        const int r0 = w * 16 + lq;
        qa[kc][0] = to_tf32(KB[r0 * KP + kc * 8 + lr] * 0.125f);
        qa[kc][1] = to_tf32(KB[(r0 + 8) * KP + kc * 8 + lr] * 0.125f);
        qa[kc][2] = to_tf32(KB[r0 * KP + kc * 8 + lr + 4] * 0.125f);
        qa[kc][3] = to_tf32(KB[(r0 + 8) * KP + kc * 8 + lr + 4] * 0.125f);
    }
    __syncthreads();

    auto issue_tile = [&](int kt, int bufi) {
        float* Kb = KB + bufi * KBW;
        float* Vb = VB + bufi * VBW;
        #pragma unroll
        for (int e = tid * 4; e < 64 * 64; e += 512) {
            const int r = e >> 6, c = e & 63;
            const int gr = kt + r;
            const int sz = (gr < cnt) ? 16 : 0;
            const int grc = (gr < NN) ? gr : (NN - 1);
            const float* ksrc = g_k + base + (size_t)grc * DD + c;
            const float* vsrc = g_v + base + (size_t)grc * DD + c;
            const uint32_t ka = (uint32_t)__cvta_generic_to_shared(Kb + r * KP + c);
            const uint32_t va = (uint32_t)__cvta_generic_to_shared(Vb + r * VP + c);
            asm volatile("cp.async.ca.shared.global [%0], [%1], 16, %2;"
                         :: "r"(ka), "l"(ksrc), "r"(sz));
            asm volatile("cp.async.ca.shared.global [%0], [%1], 16, %2;"
                         :: "r"(va), "l"(vsrc), "r"(sz));
        }
    };

    const int ntk = (cnt + 63) >> 6;
    issue_tile(0, 0);
    asm volatile("cp.async.commit_group;" ::: "memory");
    if (ntk > 1) issue_tile(64, 1);
    asm volatile("cp.async.commit_group;" ::: "memory");

    float o[8][4] = {};
    float m0 = -1e30f, m1 = -1e30f, l0 = 0.f, l1 = 0.f;

    for (int t = 0; t < ntk; t++) {
        asm volatile("cp.async.wait_group 1;" ::: "memory");
        __syncthreads();
        const int  kt = t * 64;
        const int  cur = t & 1;
        float* Ks = KB + cur * KBW;
        float* Vs = VB + cur * VBW;

        float s[8][4];
        #pragma unroll
        for (int nt = 0; nt < 8; nt++) {
            s[nt][0] = s[nt][1] = s[nt][2] = s[nt][3] = 0.f;
            #pragma unroll
            for (int kc = 0; kc < 8; kc++) {
                const uint32_t b0 =
                    __float_as_uint(Ks[(nt * 8 + lq) * KP + kc * 8 + lr]);
                const uint32_t b1 =
                    __float_as_uint(Ks[(nt * 8 + lq) * KP + kc * 8 + lr + 4]);
                mma_tf32(s[nt], qa[kc], b0, b1);
            }
        }

        float mx0 = -1e30f, mx1 = -1e30f;
        #pragma unroll
        for (int nt = 0; nt < 8; nt++) {
            const int col = kt + nt * 8 + 2 * lr;
            if (col >= cnt)     { s[nt][0] = -1e30f; s[nt][2] = -1e30f; }
            if (col + 1 >= cnt) { s[nt][1] = -1e30f; s[nt][3] = -1e30f; }
            mx0 = fmaxf(mx0, fmaxf(s[nt][0], s[nt][1]));
            mx1 = fmaxf(mx1, fmaxf(s[nt][2], s[nt][3]));
        }
        mx0 = fmaxf(mx0, __shfl_xor_sync(0xffffffffu, mx0, 1));
        mx0 = fmaxf(mx0, __shfl_xor_sync(0xffffffffu, mx0, 2));
        mx1 = fmaxf(mx1, __shfl_xor_sync(0xffffffffu, mx1, 1));
        mx1 = fmaxf(mx1, __shfl_xor_sync(0xffffffffu, mx1, 2));
        const float mn0 = fmaxf(m0, mx0), mn1 = fmaxf(m1, mx1);
        const float al0 = __expf(m0 - mn0), al1 = __expf(m1 - mn1);
        m0 = mn0; m1 = mn1;

        float ls0 = 0.f, ls1 = 0.f;
        #pragma unroll
        for (int nt = 0; nt < 8; nt++) {
            const float p0 = __expf(s[nt][0] - mn0);
            const float p1 = __expf(s[nt][1] - mn0);
            const float p2 = __expf(s[nt][2] - mn1);
            const float p3 = __expf(s[nt][3] - mn1);
            ls0 += p0 + p1; ls1 += p2 + p3;
            s[nt][0] = __uint_as_float(to_tf32(p0));
            s[nt][1] = __uint_as_float(to_tf32(p1));
            s[nt][2] = __uint_as_float(to_tf32(p2));
            s[nt][3] = __uint_as_float(to_tf32(p3));
        }
        ls0 += __shfl_xor_sync(0xffffffffu, ls0, 1);
        ls0 += __shfl_xor_sync(0xffffffffu, ls0, 2);
        ls1 += __shfl_xor_sync(0xffffffffu, ls1, 1);
        ls1 += __shfl_xor_sync(0xffffffffu, ls1, 2);
        l0 = l0 * al0 + ls0;
        l1 = l1 * al1 + ls1;
        #pragma unroll
        for (int dt = 0; dt < 8; dt++) {
            o[dt][0] *= al0; o[dt][1] *= al0;
            o[dt][2] *= al1; o[dt][3] *= al1;
        }

        const int src0 = (lane & 28) | (lr >> 1);
        const int src2 = src0 | 2;
        #pragma unroll
        for (int kc = 0; kc < 8; kc++) {
            const uint32_t P0 = __float_as_uint(s[kc][0]);
            const uint32_t P1 = __float_as_uint(s[kc][1]);
            const uint32_t P2 = __float_as_uint(s[kc][2]);
            const uint32_t P3 = __float_as_uint(s[kc][3]);
            const uint32_t u0 = __shfl_sync(0xffffffffu, P0, src0);
            const uint32_t u1 = __shfl_sync(0xffffffffu, P1, src0);
            const uint32_t u2 = __shfl_sync(0xffffffffu, P2, src0);
            const uint32_t u3 = __shfl_sync(0xffffffffu, P3, src0);
            const uint32_t v0 = __shfl_sync(0xffffffffu, P0, src2);
            const uint32_t v1 = __shfl_sync(0xffffffffu, P1, src2);
            const uint32_t v2 = __shfl_sync(0xffffffffu, P2, src2);
            const uint32_t v3 = __shfl_sync(0xffffffffu, P3, src2);
            uint32_t pa[4];
            pa[0] = (lr & 1) ? u1 : u0;
            pa[1] = (lr & 1) ? u3 : u2;
            pa[2] = (lr & 1) ? v1 : v0;
            pa[3] = (lr & 1) ? v3 : v2;
            #pragma unroll
            for (int dt = 0; dt < 8; dt++) {
                const uint32_t b0 =
                    __float_as_uint(Vs[(kc * 8 + lr) * VP + dt * 8 + lq]);
                const uint32_t b1 =
                    __float_as_uint(Vs[(kc * 8 + lr + 4) * VP + dt * 8 + lq]);
                mma_tf32(o[dt], pa, b0, b1);
            }
        }
        __syncthreads();

        if (t + 2 < ntk) issue_tile((t + 2) * 64, cur);
        asm volatile("cp.async.commit_group;" ::: "memory");
    }

    const float inv0 = 1.0f / l0, inv1 = 1.0f / l1;
    const int r0 = q0 + w * 16 + lq, r1 = r0 + 8;
    #pragma unroll
    for (int dt = 0; dt < 8; dt++) {
        const int d = h * 64 + dt * 8 + 2 * lr;
        *(float2*)(g_att + ((size_t)(b * NN + r0)) * CC + d) =
            make_float2(o[dt][0] * inv0, o[dt][1] * inv0);
        *(float2*)(g_att + ((size_t)(b * NN + r1)) * CC + d) =
            make_float2(o[dt][2] * inv1, o[dt][3] * inv1);
    }
}

// ---------------------------------------------------------------------------

extern "C" void kernel_launch(void* const* d_in, const int* in_sizes, int n_in,
                              void* d_out, int out_size)
{
    const float* x      = (const float*)d_in[0];
    const float* mask   = (const float*)d_in[1];
    const float* qkv_w  = (const float*)d_in[2];
    const float* proj_w = (const float*)d_in[3];
    const float* proj_b = (const float*)d_in[4];
    float* out = (float*)d_out;

    const int smem_attn = (2 * KBW + 2 * VBW) * (int)sizeof(float);  // 71,680 B
    cudaFuncSetAttribute(attn_kernel,
                         cudaFuncAttributeMaxDynamicSharedMemorySize, smem_attn);

    const int smem_gemm = 2 * STGW * (int)sizeof(uint32_t);          // 61,440 B
    cudaFuncSetAttribute(gemm_qkv,
                         cudaFuncAttributeMaxDynamicSharedMemorySize, smem_gemm);
    cudaFuncSetAttribute(gemm_out,
                         cudaFuncAttributeMaxDynamicSharedMemorySize, smem_gemm);

    compact_kernel<<<BB, 1024>>>(mask);
    gemm_qkv<<<384 + 768, 256, smem_gemm>>>(x, qkv_w, qkv_w + 768 * CC);
    attn_kernel<<<dim3(NN / 64, HH, BB), 128, smem_attn>>>();
    gemm_out<<<dim3(CC / 64, (BB * NN) / 128), 256, smem_gemm>>>(proj_w, proj_b, out);
}

// round 16
// speedup vs baseline: 1.1987x; 1.0309x over previous
#include <cuda_runtime.h>
#include <cuda_bf16.h>
#include <cstdint>

#define BB   2
#define HH   12
#define NN   2048
#define CC   768
#define DD   64

// Scratch (no allocations allowed)
__device__ float g_q[BB*HH*NN*DD];
__device__ float g_k[BB*HH*NN*DD];
__device__ float g_v[BB*HH*NN*DD];
__device__ float g_att[BB*NN*CC];
__device__ int   g_idx[BB*NN];
__device__ int   g_cnt[BB];

// ---------------------------------------------------------------------------
// mma helpers
// ---------------------------------------------------------------------------
__device__ __forceinline__ void mma_tf32(float* d, const uint32_t* a,
                                         uint32_t b0, uint32_t b1)
{
    asm volatile(
        "mma.sync.aligned.m16n8k8.row.col.f32.tf32.tf32.f32 "
        "{%0,%1,%2,%3},{%4,%5,%6,%7},{%8,%9},{%0,%1,%2,%3};"
        : "+f"(d[0]), "+f"(d[1]), "+f"(d[2]), "+f"(d[3])
        : "r"(a[0]), "r"(a[1]), "r"(a[2]), "r"(a[3]), "r"(b0), "r"(b1));
}

__device__ __forceinline__ void mma_bf16(float* d, const uint32_t* a,
                                         uint32_t b0, uint32_t b1)
{
    asm volatile(
        "mma.sync.aligned.m16n8k16.row.col.f32.bf16.bf16.f32 "
        "{%0,%1,%2,%3},{%4,%5,%6,%7},{%8,%9},{%0,%1,%2,%3};"
        : "+f"(d[0]), "+f"(d[1]), "+f"(d[2]), "+f"(d[3])
        : "r"(a[0]), "r"(a[1]), "r"(a[2]), "r"(a[3]), "r"(b0), "r"(b1));
}

__device__ __forceinline__ uint32_t to_tf32(float f)
{
    uint32_t u;
    asm("cvt.rna.tf32.f32 %0, %1;" : "=r"(u) : "f"(f));
    return u;
}

// split pair (x,y) into packed-bf16 hi word + lo (residual) word
__device__ __forceinline__ void cvt_pair(float x, float y,
                                         uint32_t& hi, uint32_t& lo)
{
    const __nv_bfloat16 hx = __float2bfloat16(x);
    const __nv_bfloat16 hy = __float2bfloat16(y);
    __nv_bfloat162 h; h.x = hx; h.y = hy;
    hi = *reinterpret_cast<uint32_t*>(&h);
    __nv_bfloat162 l;
    l.x = __float2bfloat16(x - __bfloat162float(hx));
    l.y = __float2bfloat16(y - __bfloat162float(hy));
    lo = *reinterpret_cast<uint32_t*>(&l);
}

// ---------------------------------------------------------------------------
// Compaction: per batch, gather indices of visible keys (mask == 0).
// ---------------------------------------------------------------------------
__global__ __launch_bounds__(1024) void compact_kernel(const float* __restrict__ mask)
{
    __shared__ int wsum[32];
    const int b = blockIdx.x;
    const int t = threadIdx.x;
    const int p0 = 2 * t, p1 = 2 * t + 1;
    const int v0 = (mask[b * NN + p0] == 0.0f) ? 1 : 0;
    const int v1 = (mask[b * NN + p1] == 0.0f) ? 1 : 0;
    const int s  = v0 + v1;

    int sc = s;
    #pragma unroll
    for (int o = 1; o < 32; o <<= 1) {
        int n = __shfl_up_sync(0xffffffffu, sc, o);
        if ((t & 31) >= o) sc += n;
    }
    if ((t & 31) == 31) wsum[t >> 5] = sc;
    __syncthreads();
    if (t < 32) {
        int w = wsum[t];
        #pragma unroll
        for (int o = 1; o < 32; o <<= 1) {
            int n = __shfl_up_sync(0xffffffffu, w, o);
            if (t >= o) w += n;
        }
        wsum[t] = w;
    }
    __syncthreads();
    const int excl = (sc - s) + ((t >= 32) ? wsum[(t >> 5) - 1] : 0);
    if (v0) g_idx[b * NN + excl] = p0;
    if (v1) g_idx[b * NN + excl + v0] = p1;
    if (t == 1023) g_cnt[b] = excl + s;
}

// ---------------------------------------------------------------------------
// Tensor-core GEMM core, 3xBF16 split, block tile 128(m) x 64(n), k-step 32,
// double-buffered smem, 8 warps (4m x 2n, 32x32 warp tiles), 2 blocks/SM.
// ---------------------------------------------------------------------------
#define GPW 20
#define ABW (128*GPW)            // words per A array (H or L)
#define BBW (64*GPW)             // words per B array
#define STGW (2*ABW + 2*BBW)     // 7680 words per stage buffer

struct TileCtx {
    int arow[4]; int aw[4]; size_t a_off[4];
    int brow[2]; int bw[2]; size_t b_off[2];
    int wm0, wn0, lq, lr;
};

__device__ __forceinline__ void gemm_core(const float* __restrict__ Ap,
                                          const float* __restrict__ W,
                                          uint32_t* su, TileCtx& cx,
                                          float acc[2][4][4])
{
    float4 pa[4], pb[2];
    #pragma unroll
    for (int p = 0; p < 4; p++) pa[p] = *(const float4*)(Ap + cx.a_off[p]);
    #pragma unroll
    for (int p = 0; p < 2; p++) pb[p] = *(const float4*)(W + cx.b_off[p]);

    int buf = 0;
    const int NK = CC / 32;
    for (int kt = 0; kt < NK; kt++) {
        uint32_t* AH = su + buf * STGW;
        uint32_t* AL = AH + ABW;
        uint32_t* BH = AL + ABW;
        uint32_t* BL = BH + BBW;

        #pragma unroll
        for (int p = 0; p < 4; p++) {
            uint32_t h0, l0, h1, l1;
            cvt_pair(pa[p].x, pa[p].y, h0, l0);
            cvt_pair(pa[p].z, pa[p].w, h1, l1);
            *(uint2*)&AH[cx.arow[p] * GPW + cx.aw[p]] = make_uint2(h0, h1);
            *(uint2*)&AL[cx.arow[p] * GPW + cx.aw[p]] = make_uint2(l0, l1);
        }
        #pragma unroll
        for (int p = 0; p < 2; p++) {
            uint32_t h0, l0, h1, l1;
            cvt_pair(pb[p].x, pb[p].y, h0, l0);
            cvt_pair(pb[p].z, pb[p].w, h1, l1);
            *(uint2*)&BH[cx.brow[p] * GPW + cx.bw[p]] = make_uint2(h0, h1);
            *(uint2*)&BL[cx.brow[p] * GPW + cx.bw[p]] = make_uint2(l0, l1);
        }
        __syncthreads();

        if (kt + 1 < NK) {
            #pragma unroll
            for (int p = 0; p < 4; p++)
                pa[p] = *(const float4*)(Ap + cx.a_off[p] + (kt + 1) * 32);
            #pragma unroll
            for (int p = 0; p < 2; p++)
                pb[p] = *(const float4*)(W + cx.b_off[p] + (kt + 1) * 32);
        }

        #pragma unroll
        for (int kb = 0; kb < 2; kb++) {
            const int wb = kb * 8;
            uint32_t aH[2][4], aL[2][4];
            #pragma unroll
            for (int i = 0; i < 2; i++) {
                const int r = cx.wm0 + i * 16 + cx.lq;
                aH[i][0] = AH[r * GPW + wb + cx.lr];
                aH[i][1] = AH[(r + 8) * GPW + wb + cx.lr];
                aH[i][2] = AH[r * GPW + wb + 4 + cx.lr];
                aH[i][3] = AH[(r + 8) * GPW + wb + 4 + cx.lr];
                aL[i][0] = AL[r * GPW + wb + cx.lr];
                aL[i][1] = AL[(r + 8) * GPW + wb + cx.lr];
                aL[i][2] = AL[r * GPW + wb + 4 + cx.lr];
                aL[i][3] = AL[(r + 8) * GPW + wb + 4 + cx.lr];
            }
            uint32_t bH[4][2], bL[4][2];
            #pragma unroll
            for (int j = 0; j < 4; j++) {
                const int n = cx.wn0 + j * 8 + cx.lq;
                bH[j][0] = BH[n * GPW + wb + cx.lr];
                bH[j][1] = BH[n * GPW + wb + 4 + cx.lr];
                bL[j][0] = BL[n * GPW + wb + cx.lr];
                bL[j][1] = BL[n * GPW + wb + 4 + cx.lr];
            }
            #pragma unroll
            for (int i = 0; i < 2; i++)
                #pragma unroll
                for (int j = 0; j < 4; j++) {
                    mma_bf16(acc[i][j], aH[i], bH[j][0], bH[j][1]);
                    mma_bf16(acc[i][j], aH[i], bL[j][0], bL[j][1]);
                    mma_bf16(acc[i][j], aL[i], bH[j][0], bH[j][1]);
                }
        }
        __syncthreads();
        buf ^= 1;
    }
}

__device__ __forceinline__ void init_ctx(TileCtx& cx, int m0, int n0,
                                         bool gather, int b, int cnt)
{
    const int tid = threadIdx.x;
    #pragma unroll
    for (int p = 0; p < 4; p++) {
        const int f = tid + p * 256;
        cx.arow[p] = f >> 3;
        cx.aw[p]   = (f & 7) * 2;
        const int col4 = (f & 7) * 4;
        if (gather) {
            const int mrow = m0 + cx.arow[p];
            const int src  = (mrow < cnt) ? g_idx[b * NN + mrow] : 0;
            cx.a_off[p] = ((size_t)(b * NN + src)) * CC + col4;
        } else {
            cx.a_off[p] = (size_t)(m0 + cx.arow[p]) * CC + col4;
        }
    }
    #pragma unroll
    for (int p = 0; p < 2; p++) {
        const int f = tid + p * 256;
        cx.brow[p] = f >> 3;
        cx.bw[p]   = (f & 7) * 2;
        cx.b_off[p] = (size_t)(n0 + cx.brow[p]) * CC + (f & 7) * 4;
    }
    const int w = tid >> 5, lane = tid & 31;
    cx.wm0 = (w >> 1) * 32;
    cx.wn0 = (w & 1) * 32;
    cx.lq  = lane >> 2;
    cx.lr  = lane & 3;
}

// ---------------------------------------------------------------------------
// Merged Q + KV projection (one launch).
// ---------------------------------------------------------------------------
__global__ __launch_bounds__(256, 2) void gemm_qkv(const float* __restrict__ X,
                                                   const float* __restrict__ Wq,
                                                   const float* __restrict__ Wkv)
{
    extern __shared__ uint32_t su[];
    const int gid = blockIdx.x;
    const bool isQ = (gid < 384);
    int n0, m0, b = 0, cnt = 0;
    const float* W;
    if (isQ) {
        n0 = (gid % 12) * 64;
        m0 = (gid / 12) * 128;
        W  = Wq;
    } else {
        const int g2 = gid - 384;
        n0 = (g2 % 24) * 64;
        m0 = ((g2 / 24) & 15) * 128;
        b  = g2 / 384;
        cnt = g_cnt[b];
        if (m0 >= cnt) return;
        W  = Wkv;
    }

    TileCtx cx;
    init_ctx(cx, m0, n0, !isQ, b, cnt);
    float acc[2][4][4] = {};
    gemm_core(X, W, su, cx, acc);

    #pragma unroll
    for (int i = 0; i < 2; i++) {
        #pragma unroll
        for (int half = 0; half < 2; half++) {
            const int m = m0 + cx.wm0 + i * 16 + cx.lq + half * 8;
            if (!isQ && m >= cnt) continue;
            #pragma unroll
            for (int j = 0; j < 4; j++) {
                const int c  = n0 + cx.wn0 + j * 8 + 2 * cx.lr;
                const float v0 = acc[i][j][half * 2];
                const float v1 = acc[i][j][half * 2 + 1];
                if (isQ) {
                    const int bpos = m >> 11, nn = m & 2047;
                    const int h = c >> 6, d = c & 63;
                    *(float2*)&g_q[(((size_t)bpos * HH + h) * NN + nn) * DD + d] =
                        make_float2(v0, v1);
                } else {
                    const bool isv = (c >= 768);
                    const int cc2 = isv ? (c - 768) : c;
                    const int h = cc2 >> 6, d = cc2 & 63;
                    float* dst = isv ? g_v : g_k;
                    *(float2*)&dst[(((size_t)b * HH + h) * NN + m) * DD + d] =
                        make_float2(v0, v1);
                }
            }
        }
    }
}

// ---------------------------------------------------------------------------
// Output projection GEMM (+bias).
// ---------------------------------------------------------------------------
__global__ __launch_bounds__(256, 2) void gemm_out(const float* __restrict__ W,
                                                   const float* __restrict__ bias,
                                                   float* __restrict__ out)
{
    extern __shared__ uint32_t su[];
    const int n0 = blockIdx.x * 64;
    const int m0 = blockIdx.y * 128;

    TileCtx cx;
    init_ctx(cx, m0, n0, false, 0, 0);
    float acc[2][4][4] = {};
    gemm_core(g_att, W, su, cx, acc);

    #pragma unroll
    for (int i = 0; i < 2; i++) {
        #pragma unroll
        for (int half = 0; half < 2; half++) {
            const int m = m0 + cx.wm0 + i * 16 + cx.lq + half * 8;
            #pragma unroll
            for (int j = 0; j < 4; j++) {
                const int c = n0 + cx.wn0 + j * 8 + 2 * cx.lr;
                *(float2*)&out[(size_t)m * CC + c] =
                    make_float2(acc[i][j][half * 2] + bias[c],
                                acc[i][j][half * 2 + 1] + bias[c + 1]);
            }
        }
    }
}

// ---------------------------------------------------------------------------
// Flash attention, tf32 mma.sync, cp.async double-buffered K/V, shuffle-P.
// Q-TILE 128 (8 warps, 256 threads): one wave of 384 blocks, 24 warps/SM,
// K/V traffic halved. Per-row numerics identical -> bit-identical output.
// ---------------------------------------------------------------------------
#define KP 68
#define VP 72
#define KBW (64*KP)
#define VBW (64*VP)

__global__ __launch_bounds__(256) void attn_kernel()
{
    extern __shared__ float sm[];
    float* KB = sm;              // 2 x 64 x KP  (also Q staging: 128 x KP)
    float* VB = sm + 2 * KBW;    // 2 x 64 x VP

    const int tid  = threadIdx.x;
    const int w    = tid >> 5, lane = tid & 31;
    const int lq   = lane >> 2;
    const int lr   = lane & 3;
    const int q0   = blockIdx.x * 128;
    const int h    = blockIdx.y;
    const int b    = blockIdx.z;
    const int cnt  = g_cnt[b];
    const size_t base = ((size_t)(b * HH + h)) * NN * DD;

    // ---- Stage Q (128 x 64, pitch KP) across both K buffers, extract
    //      loop-invariant pre-scaled tf32 A-fragments, then release buffers.
    for (int e = tid * 4; e < 128 * 64; e += 1024) {
        const int r = e >> 6, c = e & 63;
        *(float4*)(KB + r * KP + c) =
            *(const float4*)(g_q + base + (size_t)(q0 + r) * DD + c);
    }
    __syncthreads();
    uint32_t qa[8][4];
    #pragma unroll
    for (int kc = 0; kc < 8; kc++) {
        const int r0 = w * 16 + lq;
        qa[kc][0] = to_tf32(KB[r0 * KP + kc * 8 + lr] * 0.125f);
        qa[kc][1] = to_tf32(KB[(r0 + 8) * KP + kc * 8 + lr] * 0.125f);
        qa[kc][2] = to_tf32(KB[r0 * KP + kc * 8 + lr + 4] * 0.125f);
        qa[kc][3] = to_tf32(KB[(r0 + 8) * KP + kc * 8 + lr + 4] * 0.125f);
    }
    __syncthreads();

    // ---- cp.async tile loader (zero-fill past cnt) ----
    auto issue_tile = [&](int kt, int bufi) {
        float* Kb = KB + bufi * KBW;
        float* Vb = VB + bufi * VBW;
        #pragma unroll
        for (int e = tid * 4; e < 64 * 64; e += 1024) {
            const int r = e >> 6, c = e & 63;
            const int gr = kt + r;
            const int sz = (gr < cnt) ? 16 : 0;
            const int grc = (gr < NN) ? gr : (NN - 1);
            const float* ksrc = g_k + base + (size_t)grc * DD + c;
            const float* vsrc = g_v + base + (size_t)grc * DD + c;
            const uint32_t ka = (uint32_t)__cvta_generic_to_shared(Kb + r * KP + c);
            const uint32_t va = (uint32_t)__cvta_generic_to_shared(Vb + r * VP + c);
            asm volatile("cp.async.ca.shared.global [%0], [%1], 16, %2;"
                         :: "r"(ka), "l"(ksrc), "r"(sz));
            asm volatile("cp.async.ca.shared.global [%0], [%1], 16, %2;"
                         :: "r"(va), "l"(vsrc), "r"(sz));
        }
    };

    const int ntk = (cnt + 63) >> 6;
    issue_tile(0, 0);
    asm volatile("cp.async.commit_group;" ::: "memory");
    if (ntk > 1) issue_tile(64, 1);
    asm volatile("cp.async.commit_group;" ::: "memory");

    float o[8][4] = {};
    float m0 = -1e30f, m1 = -1e30f, l0 = 0.f, l1 = 0.f;

    for (int t = 0; t < ntk; t++) {
        asm volatile("cp.async.wait_group 1;" ::: "memory");
        __syncthreads();
        const int  kt = t * 64;
        const int  cur = t & 1;
        float* Ks = KB + cur * KBW;
        float* Vs = VB + cur * VBW;

        // Phase A: S = Q @ K^T
        float s[8][4];
        #pragma unroll
        for (int nt = 0; nt < 8; nt++) {
            s[nt][0] = s[nt][1] = s[nt][2] = s[nt][3] = 0.f;
            #pragma unroll
            for (int kc = 0; kc < 8; kc++) {
                const uint32_t b0 =
                    __float_as_uint(Ks[(nt * 8 + lq) * KP + kc * 8 + lr]);
                const uint32_t b1 =
                    __float_as_uint(Ks[(nt * 8 + lq) * KP + kc * 8 + lr + 4]);
                mma_tf32(s[nt], qa[kc], b0, b1);
            }
        }

        // Online softmax (identical ordering)
        float mx0 = -1e30f, mx1 = -1e30f;
        #pragma unroll
        for (int nt = 0; nt < 8; nt++) {
            const int col = kt + nt * 8 + 2 * lr;
            if (col >= cnt)     { s[nt][0] = -1e30f; s[nt][2] = -1e30f; }
            if (col + 1 >= cnt) { s[nt][1] = -1e30f; s[nt][3] = -1e30f; }
            mx0 = fmaxf(mx0, fmaxf(s[nt][0], s[nt][1]));
            mx1 = fmaxf(mx1, fmaxf(s[nt][2], s[nt][3]));
        }
        mx0 = fmaxf(mx0, __shfl_xor_sync(0xffffffffu, mx0, 1));
        mx0 = fmaxf(mx0, __shfl_xor_sync(0xffffffffu, mx0, 2));
        mx1 = fmaxf(mx1, __shfl_xor_sync(0xffffffffu, mx1, 1));
        mx1 = fmaxf(mx1, __shfl_xor_sync(0xffffffffu, mx1, 2));
        const float mn0 = fmaxf(m0, mx0), mn1 = fmaxf(m1, mx1);
        const float al0 = __expf(m0 - mn0), al1 = __expf(m1 - mn1);
        m0 = mn0; m1 = mn1;

        float ls0 = 0.f, ls1 = 0.f;
        #pragma unroll
        for (int nt = 0; nt < 8; nt++) {
            const float p0 = __expf(s[nt][0] - mn0);
            const float p1 = __expf(s[nt][1] - mn0);
            const float p2 = __expf(s[nt][2] - mn1);
            const float p3 = __expf(s[nt][3] - mn1);
            ls0 += p0 + p1; ls1 += p2 + p3;
            s[nt][0] = __uint_as_float(to_tf32(p0));
            s[nt][1] = __uint_as_float(to_tf32(p1));
            s[nt][2] = __uint_as_float(to_tf32(p2));
            s[nt][3] = __uint_as_float(to_tf32(p3));
        }
        ls0 += __shfl_xor_sync(0xffffffffu, ls0, 1);
        ls0 += __shfl_xor_sync(0xffffffffu, ls0, 2);
        ls1 += __shfl_xor_sync(0xffffffffu, ls1, 1);
        ls1 += __shfl_xor_sync(0xffffffffu, ls1, 2);
        l0 = l0 * al0 + ls0;
        l1 = l1 * al1 + ls1;
        #pragma unroll
        for (int dt = 0; dt < 8; dt++) {
            o[dt][0] *= al0; o[dt][1] *= al0;
            o[dt][2] *= al1; o[dt][3] *= al1;
        }

        // Phase B: O += P @ V (shuffle-converted P)
        const int src0 = (lane & 28) | (lr >> 1);
        const int src2 = src0 | 2;
        #pragma unroll
        for (int kc = 0; kc < 8; kc++) {
            const uint32_t P0 = __float_as_uint(s[kc][0]);
            const uint32_t P1 = __float_as_uint(s[kc][1]);
            const uint32_t P2 = __float_as_uint(s[kc][2]);
            const uint32_t P3 = __float_as_uint(s[kc][3]);
            const uint32_t u0 = __shfl_sync(0xffffffffu, P0, src0);
            const uint32_t u1 = __shfl_sync(0xffffffffu, P1, src0);
            const uint32_t u2 = __shfl_sync(0xffffffffu, P2, src0);
            const uint32_t u3 = __shfl_sync(0xffffffffu, P3, src0);
            const uint32_t v0 = __shfl_sync(0xffffffffu, P0, src2);
            const uint32_t v1 = __shfl_sync(0xffffffffu, P1, src2);
            const uint32_t v2 = __shfl_sync(0xffffffffu, P2, src2);
            const uint32_t v3 = __shfl_sync(0xffffffffu, P3, src2);
            uint32_t pa[4];
            pa[0] = (lr & 1) ? u1 : u0;
            pa[1] = (lr & 1) ? u3 : u2;
            pa[2] = (lr & 1) ? v1 : v0;
            pa[3] = (lr & 1) ? v3 : v2;
            #pragma unroll
            for (int dt = 0; dt < 8; dt++) {
                const uint32_t b0 =
                    __float_as_uint(Vs[(kc * 8 + lr) * VP + dt * 8 + lq]);
                const uint32_t b1 =
                    __float_as_uint(Vs[(kc * 8 + lr + 4) * VP + dt * 8 + lq]);
                mma_tf32(o[dt], pa, b0, b1);
            }
        }
        __syncthreads();

        if (t + 2 < ntk) issue_tile((t + 2) * 64, cur);
        asm volatile("cp.async.commit_group;" ::: "memory");
    }

    const float inv0 = 1.0f / l0, inv1 = 1.0f / l1;
    const int r0 = q0 + w * 16 + lq, r1 = r0 + 8;
    #pragma unroll
    for (int dt = 0; dt < 8; dt++) {
        const int d = h * 64 + dt * 8 + 2 * lr;
        *(float2*)(g_att + ((size_t)(b * NN + r0)) * CC + d) =
            make_float2(o[dt][0] * inv0, o[dt][1] * inv0);
        *(float2*)(g_att + ((size_t)(b * NN + r1)) * CC + d) =
            make_float2(o[dt][2] * inv1, o[dt][3] * inv1);
    }
}

// ---------------------------------------------------------------------------

extern "C" void kernel_launch(void* const* d_in, const int* in_sizes, int n_in,
                              void* d_out, int out_size)
{
    const float* x      = (const float*)d_in[0];
    const float* mask   = (const float*)d_in[1];
    const float* qkv_w  = (const float*)d_in[2];
    const float* proj_w = (const float*)d_in[3];
    const float* proj_b = (const float*)d_in[4];
    float* out = (float*)d_out;

    const int smem_attn = (2 * KBW + 2 * VBW) * (int)sizeof(float);  // 71,680 B
    cudaFuncSetAttribute(attn_kernel,
                         cudaFuncAttributeMaxDynamicSharedMemorySize, smem_attn);

    const int smem_gemm = 2 * STGW * (int)sizeof(uint32_t);          // 61,440 B
    cudaFuncSetAttribute(gemm_qkv,
                         cudaFuncAttributeMaxDynamicSharedMemorySize, smem_gemm);
    cudaFuncSetAttribute(gemm_out,
                         cudaFuncAttributeMaxDynamicSharedMemorySize, smem_gemm);

    compact_kernel<<<BB, 1024>>>(mask);
    gemm_qkv<<<384 + 768, 256, smem_gemm>>>(x, qkv_w, qkv_w + 768 * CC);
    attn_kernel<<<dim3(NN / 128, HH, BB), 256, smem_attn>>>();
    gemm_out<<<dim3(CC / 64, (BB * NN) / 128), 256, smem_gemm>>>(proj_w, proj_b, out);
}

// round 17
// speedup vs baseline: 1.2096x; 1.0091x over previous
#include <cuda_runtime.h>
#include <cuda_bf16.h>
#include <cstdint>

#define BB   2
#define HH   12
#define NN   2048
#define CC   768
#define DD   64

// Scratch (no allocations allowed)
__device__ float g_q[BB*HH*NN*DD];
__device__ float g_k[BB*HH*NN*DD];
__device__ float g_v[BB*HH*NN*DD];
__device__ int   g_idx[BB*NN];
__device__ int   g_cnt[BB];

// Pre-split bf16 hi/lo operand copies (same rounding as cvt_pair)
__device__ __nv_bfloat16 g_xh[BB*NN*CC],  g_xl[BB*NN*CC];
__device__ __nv_bfloat16 g_wqh[3*CC*CC],  g_wql[3*CC*CC];
__device__ __nv_bfloat16 g_wph[CC*CC],    g_wpl[CC*CC];
__device__ __nv_bfloat16 g_ath[BB*NN*CC], g_atl[BB*NN*CC];

// ---------------------------------------------------------------------------
// mma helpers
// ---------------------------------------------------------------------------
__device__ __forceinline__ void mma_tf32(float* d, const uint32_t* a,
                                         uint32_t b0, uint32_t b1)
{
    asm volatile(
        "mma.sync.aligned.m16n8k8.row.col.f32.tf32.tf32.f32 "
        "{%0,%1,%2,%3},{%4,%5,%6,%7},{%8,%9},{%0,%1,%2,%3};"
        : "+f"(d[0]), "+f"(d[1]), "+f"(d[2]), "+f"(d[3])
        : "r"(a[0]), "r"(a[1]), "r"(a[2]), "r"(a[3]), "r"(b0), "r"(b1));
}

__device__ __forceinline__ void mma_bf16(float* d, const uint32_t* a,
                                         uint32_t b0, uint32_t b1)
{
    asm volatile(
        "mma.sync.aligned.m16n8k16.row.col.f32.bf16.bf16.f32 "
        "{%0,%1,%2,%3},{%4,%5,%6,%7},{%8,%9},{%0,%1,%2,%3};"
        : "+f"(d[0]), "+f"(d[1]), "+f"(d[2]), "+f"(d[3])
        : "r"(a[0]), "r"(a[1]), "r"(a[2]), "r"(a[3]), "r"(b0), "r"(b1));
}

__device__ __forceinline__ uint32_t to_tf32(float f)
{
    uint32_t u;
    asm("cvt.rna.tf32.f32 %0, %1;" : "=r"(u) : "f"(f));
    return u;
}

// split pair (x,y) into packed-bf16 hi word + lo (residual) word
__device__ __forceinline__ void cvt_pair(float x, float y,
                                         uint32_t& hi, uint32_t& lo)
{
    const __nv_bfloat16 hx = __float2bfloat16(x);
    const __nv_bfloat16 hy = __float2bfloat16(y);
    __nv_bfloat162 h; h.x = hx; h.y = hy;
    hi = *reinterpret_cast<uint32_t*>(&h);
    __nv_bfloat162 l;
    l.x = __float2bfloat16(x - __bfloat162float(hx));
    l.y = __float2bfloat16(y - __bfloat162float(hy));
    lo = *reinterpret_cast<uint32_t*>(&l);
}

// ---------------------------------------------------------------------------
// Pre-convert x / qkv_w / proj_w into bf16 hi/lo arrays (one launch).
// Bit-identical rounding to the old in-loop cvt_pair.
// blocks [0,3072): x   [3072,4800): qkv_w   [4800,5376): proj_w
// ---------------------------------------------------------------------------
__global__ __launch_bounds__(256) void cvt_inputs(const float* __restrict__ x,
                                                  const float* __restrict__ wqkv,
                                                  const float* __restrict__ wp)
{
    const int gid = blockIdx.x;
    const float* src;
    __nv_bfloat16 *dh, *dl;
    int base;
    if (gid < 3072)      { src = x;    dh = g_xh;  dl = g_xl;  base = gid; }
    else if (gid < 4800) { src = wqkv; dh = g_wqh; dl = g_wql; base = gid - 3072; }
    else                 { src = wp;   dh = g_wph; dl = g_wpl; base = gid - 4800; }

    const int i = base * 256 + threadIdx.x;      // float4 index
    const float4 v = ((const float4*)src)[i];
    uint32_t h01, l01, h23, l23;
    cvt_pair(v.x, v.y, h01, l01);
    cvt_pair(v.z, v.w, h23, l23);
    ((uint2*)dh)[i] = make_uint2(h01, h23);
    ((uint2*)dl)[i] = make_uint2(l01, l23);
}

// ---------------------------------------------------------------------------
// Compaction: per batch, gather indices of visible keys (mask == 0).
// ---------------------------------------------------------------------------
__global__ __launch_bounds__(1024) void compact_kernel(const float* __restrict__ mask)
{
    __shared__ int wsum[32];
    const int b = blockIdx.x;
    const int t = threadIdx.x;
    const int p0 = 2 * t, p1 = 2 * t + 1;
    const int v0 = (mask[b * NN + p0] == 0.0f) ? 1 : 0;
    const int v1 = (mask[b * NN + p1] == 0.0f) ? 1 : 0;
    const int s  = v0 + v1;

    int sc = s;
    #pragma unroll
    for (int o = 1; o < 32; o <<= 1) {
        int n = __shfl_up_sync(0xffffffffu, sc, o);
        if ((t & 31) >= o) sc += n;
    }
    if ((t & 31) == 31) wsum[t >> 5] = sc;
    __syncthreads();
    if (t < 32) {
        int w = wsum[t];
        #pragma unroll
        for (int o = 1; o < 32; o <<= 1) {
            int n = __shfl_up_sync(0xffffffffu, w, o);
            if (t >= o) w += n;
        }
        wsum[t] = w;
    }
    __syncthreads();
    const int excl = (sc - s) + ((t >= 32) ? wsum[(t >> 5) - 1] : 0);
    if (v0) g_idx[b * NN + excl] = p0;
    if (v1) g_idx[b * NN + excl + v0] = p1;
    if (t == 1023) g_cnt[b] = excl + s;
}

// ---------------------------------------------------------------------------
// Tensor-core GEMM core, 3xBF16 split, pre-split operands, cp.async
// double-buffered loader. Block tile 128(m) x 64(n), k-step 32,
// 8 warps (4m x 2n, 32x32 warp tiles), 2 blocks/SM.
// ---------------------------------------------------------------------------
#define GPW 20
#define ABW (128*GPW)            // words per A array (H or L)
#define BBW (64*GPW)             // words per B array
#define STGW (2*ABW + 2*BBW)     // 7680 words per stage buffer

struct TileCtx {
    int ar[2]; int ac[2]; size_t a_off[2];   // bf16-element offsets
    int br;    int bc;    size_t b_off;
    int wm0, wn0, lq, lr;
};

__device__ __forceinline__ void init_ctx(TileCtx& cx, int m0, int n0,
                                         bool gather, int b, int cnt)
{
    const int tid = threadIdx.x;
    #pragma unroll
    for (int p = 0; p < 2; p++) {
        const int c = tid + p * 256;         // chunk 0..511
        cx.ar[p] = c >> 2;                   // row 0..127
        cx.ac[p] = c & 3;                    // 16B chunk within 64B row-slice
        const int col = cx.ac[p] * 8;        // bf16 column
        if (gather) {
            const int mrow = m0 + cx.ar[p];
            const int src  = (mrow < cnt) ? g_idx[b * NN + mrow] : 0;
            cx.a_off[p] = ((size_t)(b * NN + src)) * CC + col;
        } else {
            cx.a_off[p] = (size_t)(m0 + cx.ar[p]) * CC + col;
        }
    }
    cx.br = tid >> 2;                        // 0..63
    cx.bc = tid & 3;
    cx.b_off = (size_t)(n0 + cx.br) * CC + cx.bc * 8;

    const int w = tid >> 5, lane = tid & 31;
    cx.wm0 = (w >> 1) * 32;
    cx.wn0 = (w & 1) * 32;
    cx.lq  = lane >> 2;
    cx.lr  = lane & 3;
}

__device__ __forceinline__ void gemm_core(const __nv_bfloat16* __restrict__ Ah,
                                          const __nv_bfloat16* __restrict__ Al,
                                          const __nv_bfloat16* __restrict__ Bh,
                                          const __nv_bfloat16* __restrict__ Bl,
                                          uint32_t* su, TileCtx& cx,
                                          float acc[2][4][4])
{
    auto issue = [&](int kt, int buf) {
        uint32_t* AH = su + buf * STGW;
        uint32_t* AL = AH + ABW;
        uint32_t* BH = AL + ABW;
        uint32_t* BL = BH + BBW;
        #pragma unroll
        for (int p = 0; p < 2; p++) {
            const size_t so = cx.a_off[p] + kt * 32;
            const uint32_t dh =
                (uint32_t)__cvta_generic_to_shared(&AH[cx.ar[p] * GPW + cx.ac[p] * 4]);
            asm volatile("cp.async.ca.shared.global [%0], [%1], 16;"
                         :: "r"(dh), "l"(Ah + so));
            const uint32_t dl =
                (uint32_t)__cvta_generic_to_shared(&AL[cx.ar[p] * GPW + cx.ac[p] * 4]);
            asm volatile("cp.async.ca.shared.global [%0], [%1], 16;"
                         :: "r"(dl), "l"(Al + so));
        }
        {
            const size_t so = cx.b_off + kt * 32;
            const uint32_t dh =
                (uint32_t)__cvta_generic_to_shared(&BH[cx.br * GPW + cx.bc * 4]);
            asm volatile("cp.async.ca.shared.global [%0], [%1], 16;"
                         :: "r"(dh), "l"(Bh + so));
            const uint32_t dl =
                (uint32_t)__cvta_generic_to_shared(&BL[cx.br * GPW + cx.bc * 4]);
            asm volatile("cp.async.ca.shared.global [%0], [%1], 16;"
                         :: "r"(dl), "l"(Bl + so));
        }
    };

    const int NK = CC / 32;                  // 24
    issue(0, 0);
    asm volatile("cp.async.commit_group;" ::: "memory");
    issue(1, 1);
    asm volatile("cp.async.commit_group;" ::: "memory");

    for (int kt = 0; kt < NK; kt++) {
        asm volatile("cp.async.wait_group 1;" ::: "memory");
        __syncthreads();
        const int buf = kt & 1;
        uint32_t* AH = su + buf * STGW;
        uint32_t* AL = AH + ABW;
        uint32_t* BH = AL + ABW;
        uint32_t* BL = BH + BBW;

        #pragma unroll
        for (int kb = 0; kb < 2; kb++) {
            const int wb = kb * 8;
            uint32_t aH[2][4], aL[2][4];
            #pragma unroll
            for (int i = 0; i < 2; i++) {
                const int r = cx.wm0 + i * 16 + cx.lq;
                aH[i][0] = AH[r * GPW + wb + cx.lr];
                aH[i][1] = AH[(r + 8) * GPW + wb + cx.lr];
                aH[i][2] = AH[r * GPW + wb + 4 + cx.lr];
                aH[i][3] = AH[(r + 8) * GPW + wb + 4 + cx.lr];
                aL[i][0] = AL[r * GPW + wb + cx.lr];
                aL[i][1] = AL[(r + 8) * GPW + wb + cx.lr];
                aL[i][2] = AL[r * GPW + wb + 4 + cx.lr];
                aL[i][3] = AL[(r + 8) * GPW + wb + 4 + cx.lr];
            }
            uint32_t bH[4][2], bL[4][2];
            #pragma unroll
            for (int j = 0; j < 4; j++) {
                const int n = cx.wn0 + j * 8 + cx.lq;
                bH[j][0] = BH[n * GPW + wb + cx.lr];
                bH[j][1] = BH[n * GPW + wb + 4 + cx.lr];
                bL[j][0] = BL[n * GPW + wb + cx.lr];
                bL[j][1] = BL[n * GPW + wb + 4 + cx.lr];
            }
            #pragma unroll
            for (int i = 0; i < 2; i++)
                #pragma unroll
                for (int j = 0; j < 4; j++) {
                    mma_bf16(acc[i][j], aH[i], bH[j][0], bH[j][1]);
                    mma_bf16(acc[i][j], aH[i], bL[j][0], bL[j][1]);
                    mma_bf16(acc[i][j], aL[i], bH[j][0], bH[j][1]);
                }
        }
        __syncthreads();
        if (kt + 2 < NK) issue(kt + 2, buf);
        asm volatile("cp.async.commit_group;" ::: "memory");
    }
}

// ---------------------------------------------------------------------------
// Merged Q + KV projection (one launch).
// ---------------------------------------------------------------------------
__global__ __launch_bounds__(256, 2) void gemm_qkv()
{
    extern __shared__ uint32_t su[];
    const int gid = blockIdx.x;
    const bool isQ = (gid < 384);
    int n0, m0, b = 0, cnt = 0, nbase;
    if (isQ) {
        n0 = (gid % 12) * 64;
        m0 = (gid / 12) * 128;
        nbase = 0;
    } else {
        const int g2 = gid - 384;
        n0 = (g2 % 24) * 64;
        m0 = ((g2 / 24) & 15) * 128;
        b  = g2 / 384;
        cnt = g_cnt[b];
        if (m0 >= cnt) return;
        nbase = 768;
    }

    TileCtx cx;
    init_ctx(cx, m0, nbase + n0, !isQ, b, cnt);   // W rows offset by nbase
    // note: n0 used below for epilogue column; B offsets use nbase+n0 rows
    float acc[2][4][4] = {};
    gemm_core(g_xh, g_xl, g_wqh, g_wql, su, cx, acc);

    #pragma unroll
    for (int i = 0; i < 2; i++) {
        #pragma unroll
        for (int half = 0; half < 2; half++) {
            const int m = m0 + cx.wm0 + i * 16 + cx.lq + half * 8;
            if (!isQ && m >= cnt) continue;
            #pragma unroll
            for (int j = 0; j < 4; j++) {
                const int c  = n0 + cx.wn0 + j * 8 + 2 * cx.lr;
                const float v0 = acc[i][j][half * 2];
                const float v1 = acc[i][j][half * 2 + 1];
                if (isQ) {
                    const int bpos = m >> 11, nn = m & 2047;
                    const int h = c >> 6, d = c & 63;
                    *(float2*)&g_q[(((size_t)bpos * HH + h) * NN + nn) * DD + d] =
                        make_float2(v0, v1);
                } else {
                    const bool isv = (c >= 768);
                    const int cc2 = isv ? (c - 768) : c;
                    const int h = cc2 >> 6, d = cc2 & 63;
                    float* dst = isv ? g_v : g_k;
                    *(float2*)&dst[(((size_t)b * HH + h) * NN + m) * DD + d] =
                        make_float2(v0, v1);
                }
            }
        }
    }
}

// ---------------------------------------------------------------------------
// Output projection GEMM (+bias).
// ---------------------------------------------------------------------------
__global__ __launch_bounds__(256, 2) void gemm_out(const float* __restrict__ bias,
                                                   float* __restrict__ out)
{
    extern __shared__ uint32_t su[];
    const int n0 = blockIdx.x * 64;
    const int m0 = blockIdx.y * 128;

    TileCtx cx;
    init_ctx(cx, m0, n0, false, 0, 0);
    float acc[2][4][4] = {};
    gemm_core(g_ath, g_atl, g_wph, g_wpl, su, cx, acc);

    #pragma unroll
    for (int i = 0; i < 2; i++) {
        #pragma unroll
        for (int half = 0; half < 2; half++) {
            const int m = m0 + cx.wm0 + i * 16 + cx.lq + half * 8;
            #pragma unroll
            for (int j = 0; j < 4; j++) {
                const int c = n0 + cx.wn0 + j * 8 + 2 * cx.lr;
                *(float2*)&out[(size_t)m * CC + c] =
                    make_float2(acc[i][j][half * 2] + bias[c],
                                acc[i][j][half * 2 + 1] + bias[c + 1]);
            }
        }
    }
}

// ---------------------------------------------------------------------------
// Flash attention, tf32 mma.sync, cp.async double-buffered K/V, shuffle-P,
// 128-row Q tile. Epilogue writes att directly as bf16 hi/lo (same cvt_pair
// rounding the GEMM loader used to apply -> bit-identical downstream).
// ---------------------------------------------------------------------------
#define KP 68
#define VP 72
#define KBW (64*KP)
#define VBW (64*VP)

__global__ __launch_bounds__(256) void attn_kernel()
{
    extern __shared__ float sm[];
    float* KB = sm;              // 2 x 64 x KP  (also Q staging: 128 x KP)
    float* VB = sm + 2 * KBW;    // 2 x 64 x VP

    const int tid  = threadIdx.x;
    const int w    = tid >> 5, lane = tid & 31;
    const int lq   = lane >> 2;
    const int lr   = lane & 3;
    const int q0   = blockIdx.x * 128;
    const int h    = blockIdx.y;
    const int b    = blockIdx.z;
    const int cnt  = g_cnt[b];
    const size_t base = ((size_t)(b * HH + h)) * NN * DD;

    for (int e = tid * 4; e < 128 * 64; e += 1024) {
        const int r = e >> 6, c = e & 63;
        *(float4*)(KB + r * KP + c) =
            *(const float4*)(g_q + base + (size_t)(q0 + r) * DD + c);
    }
    __syncthreads();
    uint32_t qa[8][4];
    #pragma unroll
    for (int kc = 0; kc < 8; kc++) {
        const int r0 = w * 16 + lq;
        qa[kc][0] = to_tf32(KB[r0 * KP + kc * 8 + lr] * 0.125f);
        qa[kc][1] = to_tf32(KB[(r0 + 8) * KP + kc * 8 + lr] * 0.125f);
        qa[kc][2] = to_tf32(KB[r0 * KP + kc * 8 + lr + 4] * 0.125f);
        qa[kc][3] = to_tf32(KB[(r0 + 8) * KP + kc * 8 + lr + 4] * 0.125f);
    }
    __syncthreads();

    auto issue_tile = [&](int kt, int bufi) {
        float* Kb = KB + bufi * KBW;
        float* Vb = VB + bufi * VBW;
        #pragma unroll
        for (int e = tid * 4; e < 64 * 64; e += 1024) {
            const int r = e >> 6, c = e & 63;
            const int gr = kt + r;
            const int sz = (gr < cnt) ? 16 : 0;
            const int grc = (gr < NN) ? gr : (NN - 1);
            const float* ksrc = g_k + base + (size_t)grc * DD + c;
            const float* vsrc = g_v + base + (size_t)grc * DD + c;
            const uint32_t ka = (uint32_t)__cvta_generic_to_shared(Kb + r * KP + c);
            const uint32_t va = (uint32_t)__cvta_generic_to_shared(Vb + r * VP + c);
            asm volatile("cp.async.ca.shared.global [%0], [%1], 16, %2;"
                         :: "r"(ka), "l"(ksrc), "r"(sz));
            asm volatile("cp.async.ca.shared.global [%0], [%1], 16, %2;"
                         :: "r"(va), "l"(vsrc), "r"(sz));
        }
    };

    const int ntk = (cnt + 63) >> 6;
    issue_tile(0, 0);
    asm volatile("cp.async.commit_group;" ::: "memory");
    if (ntk > 1) issue_tile(64, 1);
    asm volatile("cp.async.commit_group;" ::: "memory");

    float o[8][4] = {};
    float m0 = -1e30f, m1 = -1e30f, l0 = 0.f, l1 = 0.f;

    for (int t = 0; t < ntk; t++) {
        asm volatile("cp.async.wait_group 1;" ::: "memory");
        __syncthreads();
        const int  kt = t * 64;
        const int  cur = t & 1;
        float* Ks = KB + cur * KBW;
        float* Vs = VB + cur * VBW;

        float s[8][4];
        #pragma unroll
        for (int nt = 0; nt < 8; nt++) {
            s[nt][0] = s[nt][1] = s[nt][2] = s[nt][3] = 0.f;
            #pragma unroll
            for (int kc = 0; kc < 8; kc++) {
                const uint32_t b0 =
                    __float_as_uint(Ks[(nt * 8 + lq) * KP + kc * 8 + lr]);
                const uint32_t b1 =
                    __float_as_uint(Ks[(nt * 8 + lq) * KP + kc * 8 + lr + 4]);
                mma_tf32(s[nt], qa[kc], b0, b1);
            }
        }

        float mx0 = -1e30f, mx1 = -1e30f;
        #pragma unroll
        for (int nt = 0; nt < 8; nt++) {
            const int col = kt + nt * 8 + 2 * lr;
            if (col >= cnt)     { s[nt][0] = -1e30f; s[nt][2] = -1e30f; }
            if (col + 1 >= cnt) { s[nt][1] = -1e30f; s[nt][3] = -1e30f; }
            mx0 = fmaxf(mx0, fmaxf(s[nt][0], s[nt][1]));
            mx1 = fmaxf(mx1, fmaxf(s[nt][2], s[nt][3]));
        }
        mx0 = fmaxf(mx0, __shfl_xor_sync(0xffffffffu, mx0, 1));
        mx0 = fmaxf(mx0, __shfl_xor_sync(0xffffffffu, mx0, 2));
        mx1 = fmaxf(mx1, __shfl_xor_sync(0xffffffffu, mx1, 1));
        mx1 = fmaxf(mx1, __shfl_xor_sync(0xffffffffu, mx1, 2));
        const float mn0 = fmaxf(m0, mx0), mn1 = fmaxf(m1, mx1);
        const float al0 = __expf(m0 - mn0), al1 = __expf(m1 - mn1);
        m0 = mn0; m1 = mn1;

        float ls0 = 0.f, ls1 = 0.f;
        #pragma unroll
        for (int nt = 0; nt < 8; nt++) {
            const float p0 = __expf(s[nt][0] - mn0);
            const float p1 = __expf(s[nt][1] - mn0);
            const float p2 = __expf(s[nt][2] - mn1);
            const float p3 = __expf(s[nt][3] - mn1);
            ls0 += p0 + p1; ls1 += p2 + p3;
            s[nt][0] = __uint_as_float(to_tf32(p0));
            s[nt][1] = __uint_as_float(to_tf32(p1));
            s[nt][2] = __uint_as_float(to_tf32(p2));
            s[nt][3] = __uint_as_float(to_tf32(p3));
        }
        ls0 += __shfl_xor_sync(0xffffffffu, ls0, 1);
        ls0 += __shfl_xor_sync(0xffffffffu, ls0, 2);
        ls1 += __shfl_xor_sync(0xffffffffu, ls1, 1);
        ls1 += __shfl_xor_sync(0xffffffffu, ls1, 2);
        l0 = l0 * al0 + ls0;
        l1 = l1 * al1 + ls1;
        #pragma unroll
        for (int dt = 0; dt < 8; dt++) {
            o[dt][0] *= al0; o[dt][1] *= al0;
            o[dt][2] *= al1; o[dt][3] *= al1;
        }

        const int src0 = (lane & 28) | (lr >> 1);
        const int src2 = src0 | 2;
        #pragma unroll
        for (int kc = 0; kc < 8; kc++) {
            const uint32_t P0 = __float_as_uint(s[kc][0]);
            const uint32_t P1 = __float_as_uint(s[kc][1]);
            const uint32_t P2 = __float_as_uint(s[kc][2]);
            const uint32_t P3 = __float_as_uint(s[kc][3]);
            const uint32_t u0 = __shfl_sync(0xffffffffu, P0, src0);
            const uint32_t u1 = __shfl_sync(0xffffffffu, P1, src0);
            const uint32_t u2 = __shfl_sync(0xffffffffu, P2, src0);
            const uint32_t u3 = __shfl_sync(0xffffffffu, P3, src0);
            const uint32_t v0 = __shfl_sync(0xffffffffu, P0, src2);
            const uint32_t v1 = __shfl_sync(0xffffffffu, P1, src2);
            const uint32_t v2 = __shfl_sync(0xffffffffu, P2, src2);
            const uint32_t v3 = __shfl_sync(0xffffffffu, P3, src2);
            uint32_t pa[4];
            pa[0] = (lr & 1) ? u1 : u0;
            pa[1] = (lr & 1) ? u3 : u2;
            pa[2] = (lr & 1) ? v1 : v0;
            pa[3] = (lr & 1) ? v3 : v2;
            #pragma unroll
            for (int dt = 0; dt < 8; dt++) {
                const uint32_t b0 =
                    __float_as_uint(Vs[(kc * 8 + lr) * VP + dt * 8 + lq]);
                const uint32_t b1 =
                    __float_as_uint(Vs[(kc * 8 + lr + 4) * VP + dt * 8 + lq]);
                mma_tf32(o[dt], pa, b0, b1);
            }
        }
        __syncthreads();

        if (t + 2 < ntk) issue_tile((t + 2) * 64, cur);
        asm volatile("cp.async.commit_group;" ::: "memory");
    }

    // Epilogue: normalize, split to bf16 hi/lo, store att operand directly.
    const float inv0 = 1.0f / l0, inv1 = 1.0f / l1;
    const int r0 = q0 + w * 16 + lq, r1 = r0 + 8;
    uint32_t* ATH = (uint32_t*)g_ath;
    uint32_t* ATL = (uint32_t*)g_atl;
    #pragma unroll
    for (int dt = 0; dt < 8; dt++) {
        const int d = h * 64 + dt * 8 + 2 * lr;
        uint32_t hw, lw;
        cvt_pair(o[dt][0] * inv0, o[dt][1] * inv0, hw, lw);
        const size_t w0 = (((size_t)(b * NN + r0)) * CC + d) >> 1;
        ATH[w0] = hw; ATL[w0] = lw;
        cvt_pair(o[dt][2] * inv1, o[dt][3] * inv1, hw, lw);
        const size_t w1 = (((size_t)(b * NN + r1)) * CC + d) >> 1;
        ATH[w1] = hw; ATL[w1] = lw;
    }
}

// ---------------------------------------------------------------------------

extern "C" void kernel_launch(void* const* d_in, const int* in_sizes, int n_in,
                              void* d_out, int out_size)
{
    const float* x      = (const float*)d_in[0];
    const float* mask   = (const float*)d_in[1];
    const float* qkv_w  = (const float*)d_in[2];
    const float* proj_w = (const float*)d_in[3];
    const float* proj_b = (const float*)d_in[4];
    float* out = (float*)d_out;

    const int smem_attn = (2 * KBW + 2 * VBW) * (int)sizeof(float);  // 71,680 B
    cudaFuncSetAttribute(attn_kernel,
                         cudaFuncAttributeMaxDynamicSharedMemorySize, smem_attn);

    const int smem_gemm = 2 * STGW * (int)sizeof(uint32_t);          // 61,440 B
    cudaFuncSetAttribute(gemm_qkv,
                         cudaFuncAttributeMaxDynamicSharedMemorySize, smem_gemm);
    cudaFuncSetAttribute(gemm_out,
                         cudaFuncAttributeMaxDynamicSharedMemorySize, smem_gemm);

    cvt_inputs<<<5376, 256>>>(x, qkv_w, proj_w);
    compact_kernel<<<BB, 1024>>>(mask);
    gemm_qkv<<<384 + 768, 256, smem_gemm>>>();
    attn_kernel<<<dim3(NN / 128, HH, BB), 256, smem_attn>>>();
    gemm_out<<<dim3(CC / 64, (BB * NN) / 128), 256, smem_gemm>>>(proj_b, out);
}